// round 2
// baseline (speedup 1.0000x reference)
#include <cuda_runtime.h>
#include <math_constants.h>

// Problem constants (fixed by the dataset)
#define NN   50000
#define EE   600000
#define EP   (EE + NN)     // edges + self loops = 650000
#define FIN  128
#define HC   256           // H*C = 4*64
#define NG   64            // graphs
#define NCLS 3

// ---------------- device scratch (no allocation allowed) ----------------
__device__ float g_XL[(size_t)NN * HC];   // source transform
__device__ float g_XR[(size_t)NN * HC];   // target transform
__device__ float g_H [(size_t)NN * HC];   // layer output / next layer input
__device__ int   g_deg[NN];
__device__ int   g_off[NN];
__device__ int   g_cur[NN];
__device__ int   g_esrc[EP];
__device__ float    g_psum[NG * HC];
__device__ unsigned g_pmax[NG * HC];
__device__ int      g_cnt[NG];

// order-preserving float<->uint key for atomicMax on floats
__device__ __forceinline__ unsigned fkey(float f) {
    unsigned b = __float_as_uint(f);
    return (b & 0x80000000u) ? ~b : (b | 0x80000000u);
}
__device__ __forceinline__ float fdekey(unsigned u) {
    return (u & 0x80000000u) ? __uint_as_float(u & 0x7FFFFFFFu)
                             : __uint_as_float(~u);
}

// ---------------- init ----------------
__global__ void k_init() {
    int i = blockIdx.x * blockDim.x + threadIdx.x;
    int stride = gridDim.x * blockDim.x;
    for (int j = i; j < NN; j += stride) g_deg[j] = 0;
    for (int j = i; j < NG * HC; j += stride) { g_psum[j] = 0.f; g_pmax[j] = 0x007FFFFFu; } // fkey(-inf)
    for (int j = i; j < NG; j += stride) g_cnt[j] = 0;
}

// ---------------- CSR build: histogram, scan, scatter ----------------
__global__ void k_deg(const int* __restrict__ ei) {
    int i = blockIdx.x * blockDim.x + threadIdx.x;
    if (i >= EP) return;
    int d = (i < EE) ? ei[EE + i] : (i - EE);
    atomicAdd(&g_deg[d], 1);
}

// single-block hierarchical scan over NN elements (exclusive prefix)
__global__ void k_scan() {
    __shared__ int wsum[32];
    __shared__ int tot;
    int tid = threadIdx.x, lane = tid & 31, wid = tid >> 5;
    int running = 0;
    for (int base = 0; base < NN; base += 1024) {
        int i = base + tid;
        int v = (i < NN) ? g_deg[i] : 0;
        // warp inclusive scan
        int x = v;
        #pragma unroll
        for (int o = 1; o < 32; o <<= 1) {
            int t = __shfl_up_sync(0xFFFFFFFFu, x, o);
            if (lane >= o) x += t;
        }
        if (lane == 31) wsum[wid] = x;
        __syncthreads();
        if (wid == 0) {
            int orig = wsum[lane];
            int y = orig;
            #pragma unroll
            for (int o = 1; o < 32; o <<= 1) {
                int t = __shfl_up_sync(0xFFFFFFFFu, y, o);
                if (lane >= o) y += t;
            }
            wsum[lane] = y - orig;   // exclusive per-warp offsets
        }
        __syncthreads();
        int incl = x + wsum[wid];
        if (i < NN) {
            int ex = running + incl - v;
            g_off[i] = ex;
            g_cur[i] = ex;
        }
        if (tid == 1023) tot = incl;
        __syncthreads();
        running += tot;
    }
}

__global__ void k_scatter(const int* __restrict__ ei) {
    int i = blockIdx.x * blockDim.x + threadIdx.x;
    if (i >= EP) return;
    int s, d;
    if (i < EE) { s = ei[i]; d = ei[EE + i]; }
    else        { s = d = i - EE; }
    int pos = atomicAdd(&g_cur[d], 1);
    g_esrc[pos] = s;
}

// ---------------- dual GEMM: XL = act(A)@W1 + b1, XR = act(A)@W2 + b2 ----------------
// A: NN x K row-major (nullptr -> g_H). W: K x 256 row-major.
template <int K, bool RELU>
__global__ void k_dualgemm(const float* __restrict__ Ain,
                           const float* __restrict__ W1, const float* __restrict__ b1,
                           const float* __restrict__ W2, const float* __restrict__ b2) {
    __shared__ float As[16][68];   // [k][m], padded (68 floats = 272B, 16B aligned rows)
    __shared__ float B1[16][64];
    __shared__ float B2[16][64];

    const float* A = Ain ? Ain : g_H;
    int tid = threadIdx.x;
    int m0 = blockIdx.x * 64, n0 = blockIdx.y * 64;
    int tx = tid & 15, ty = tid >> 4;

    float acc1[4][4], acc2[4][4];
    #pragma unroll
    for (int i = 0; i < 4; i++)
        #pragma unroll
        for (int j = 0; j < 4; j++) { acc1[i][j] = 0.f; acc2[i][j] = 0.f; }

    int lr = tid >> 2;            // 0..63 (A row within tile)
    int lc = (tid & 3) * 4;       // 0,4,8,12 (A col within k-tile)
    int br = tid >> 4;            // 0..15 (B row)
    int bc = (tid & 15) * 4;      // B col

    for (int k0 = 0; k0 < K; k0 += 16) {
        float4 av = make_float4(0.f, 0.f, 0.f, 0.f);
        int arow = m0 + lr;
        if (arow < NN)
            av = *(const float4*)&A[(size_t)arow * K + k0 + lc];
        if (RELU) {
            av.x = fmaxf(av.x, 0.f); av.y = fmaxf(av.y, 0.f);
            av.z = fmaxf(av.z, 0.f); av.w = fmaxf(av.w, 0.f);
        }
        As[lc + 0][lr] = av.x; As[lc + 1][lr] = av.y;
        As[lc + 2][lr] = av.z; As[lc + 3][lr] = av.w;

        float4 b1v = *(const float4*)&W1[(size_t)(k0 + br) * HC + n0 + bc];
        float4 b2v = *(const float4*)&W2[(size_t)(k0 + br) * HC + n0 + bc];
        *(float4*)&B1[br][bc] = b1v;
        *(float4*)&B2[br][bc] = b2v;
        __syncthreads();

        #pragma unroll
        for (int kk = 0; kk < 16; kk++) {
            float4 a4 = *(float4*)&As[kk][ty * 4];
            float4 p4 = *(float4*)&B1[kk][tx * 4];
            float4 q4 = *(float4*)&B2[kk][tx * 4];
            float a[4] = {a4.x, a4.y, a4.z, a4.w};
            float p[4] = {p4.x, p4.y, p4.z, p4.w};
            float q[4] = {q4.x, q4.y, q4.z, q4.w};
            #pragma unroll
            for (int i = 0; i < 4; i++)
                #pragma unroll
                for (int j = 0; j < 4; j++) {
                    acc1[i][j] = fmaf(a[i], p[j], acc1[i][j]);
                    acc2[i][j] = fmaf(a[i], q[j], acc2[i][j]);
                }
        }
        __syncthreads();
    }

    float4 bb1 = *(const float4*)&b1[n0 + tx * 4];
    float4 bb2 = *(const float4*)&b2[n0 + tx * 4];
    float bv1[4] = {bb1.x, bb1.y, bb1.z, bb1.w};
    float bv2[4] = {bb2.x, bb2.y, bb2.z, bb2.w};
    #pragma unroll
    for (int i = 0; i < 4; i++) {
        int row = m0 + ty * 4 + i;
        if (row < NN) {
            float4 o1 = make_float4(acc1[i][0] + bv1[0], acc1[i][1] + bv1[1],
                                    acc1[i][2] + bv1[2], acc1[i][3] + bv1[3]);
            float4 o2 = make_float4(acc2[i][0] + bv2[0], acc2[i][1] + bv2[1],
                                    acc2[i][2] + bv2[2], acc2[i][3] + bv2[3]);
            *(float4*)&g_XL[(size_t)row * HC + n0 + tx * 4] = o1;
            *(float4*)&g_XR[(size_t)row * HC + n0 + tx * 4] = o2;
        }
    }
}

// ---------------- warp-per-node edge softmax + aggregation (online softmax) ----------------
__global__ void k_agg(const float* __restrict__ att, const float* __restrict__ bias) {
    int gt = blockIdx.x * blockDim.x + threadIdx.x;
    int node = gt >> 5;
    int lane = gt & 31;
    if (node >= NN) return;

    int fb = lane * 8;   // this lane owns features [fb, fb+8); head = lane/8 (8|64 so single head)

    float4 x0 = *(const float4*)&g_XR[(size_t)node * HC + fb];
    float4 x1 = *(const float4*)&g_XR[(size_t)node * HC + fb + 4];
    float xr[8] = {x0.x, x0.y, x0.z, x0.w, x1.x, x1.y, x1.z, x1.w};
    float4 a0 = *(const float4*)&att[fb];
    float4 a1 = *(const float4*)&att[fb + 4];
    float at[8] = {a0.x, a0.y, a0.z, a0.w, a1.x, a1.y, a1.z, a1.w};

    float acc[8];
    #pragma unroll
    for (int j = 0; j < 8; j++) acc[j] = 0.f;
    float m = -CUDART_INF_F, den = 0.f;

    int st = g_off[node];
    int en = st + g_deg[node];

    for (int e = st; e < en; e++) {
        int s = g_esrc[e];
        float4 v0 = *(const float4*)&g_XL[(size_t)s * HC + fb];
        float4 v1 = *(const float4*)&g_XL[(size_t)s * HC + fb + 4];
        float v[8] = {v0.x, v0.y, v0.z, v0.w, v1.x, v1.y, v1.z, v1.w};

        float ps = 0.f;
        #pragma unroll
        for (int j = 0; j < 8; j++) {
            float t = v[j] + xr[j];
            t = (t > 0.f) ? t : 0.2f * t;   // leaky_relu 0.2
            ps = fmaf(t, at[j], ps);
        }
        // reduce over the 8 lanes of this head
        ps += __shfl_xor_sync(0xFFFFFFFFu, ps, 1);
        ps += __shfl_xor_sync(0xFFFFFFFFu, ps, 2);
        ps += __shfl_xor_sync(0xFFFFFFFFu, ps, 4);

        float mn = fmaxf(m, ps);
        float scale = __expf(m - mn);   // 0 on first edge (m=-inf)
        float w = __expf(ps - mn);
        den = den * scale + w;
        #pragma unroll
        for (int j = 0; j < 8; j++) acc[j] = fmaf(acc[j], scale, w * v[j]);
        m = mn;
    }

    float inv = 1.f / den;
    float4 bb0 = *(const float4*)&bias[fb];
    float4 bb1 = *(const float4*)&bias[fb + 4];
    float bs[8] = {bb0.x, bb0.y, bb0.z, bb0.w, bb1.x, bb1.y, bb1.z, bb1.w};
    float4 o0 = make_float4(acc[0] * inv + bs[0], acc[1] * inv + bs[1],
                            acc[2] * inv + bs[2], acc[3] * inv + bs[3]);
    float4 o1 = make_float4(acc[4] * inv + bs[4], acc[5] * inv + bs[5],
                            acc[6] * inv + bs[6], acc[7] * inv + bs[7]);
    *(float4*)&g_H[(size_t)node * HC + fb]     = o0;
    *(float4*)&g_H[(size_t)node * HC + fb + 4] = o1;
}

// ---------------- pooling ----------------
__global__ void k_cnt(const int* __restrict__ batch) {
    int i = blockIdx.x * blockDim.x + threadIdx.x;
    if (i < NN) atomicAdd(&g_cnt[batch[i]], 1);
}

__global__ void k_pool(const int* __restrict__ batch) {
    int f = threadIdx.x;                 // 256 features
    int n0 = blockIdx.x * 256;
    int n1 = min(n0 + 256, NN);
    int curg = -1;
    float s = 0.f, mx = -CUDART_INF_F;
    for (int n = n0; n < n1; n++) {
        int g = batch[n];
        float v = g_H[(size_t)n * HC + f];
        if (g != curg) {
            if (curg >= 0) {
                atomicAdd(&g_psum[curg * HC + f], s);
                atomicMax(&g_pmax[curg * HC + f], fkey(mx));
            }
            curg = g; s = 0.f; mx = -CUDART_INF_F;
        }
        s += v;
        mx = fmaxf(mx, v);
    }
    if (curg >= 0) {
        atomicAdd(&g_psum[curg * HC + f], s);
        atomicMax(&g_pmax[curg * HC + f], fkey(mx));
    }
}

// ---------------- classifier + softmax ----------------
__global__ void k_final(const float* __restrict__ Wout, const float* __restrict__ bout,
                        float* __restrict__ out) {
    int g = threadIdx.x;
    if (g >= NG) return;
    float c = (float)max(g_cnt[g], 1);
    float inv_c = 1.f / c;
    float l0 = bout[0], l1 = bout[1], l2 = bout[2];
    for (int f = 0; f < HC; f++) {
        float p = g_psum[g * HC + f] * inv_c + fdekey(g_pmax[g * HC + f]);
        l0 = fmaf(p, Wout[f * NCLS + 0], l0);
        l1 = fmaf(p, Wout[f * NCLS + 1], l1);
        l2 = fmaf(p, Wout[f * NCLS + 2], l2);
    }
    float mx = fmaxf(l0, fmaxf(l1, l2));
    float e0 = __expf(l0 - mx), e1 = __expf(l1 - mx), e2 = __expf(l2 - mx);
    float inv = 1.f / (e0 + e1 + e2);
    out[g * NCLS + 0] = e0 * inv;
    out[g * NCLS + 1] = e1 * inv;
    out[g * NCLS + 2] = e2 * inv;
}

// ---------------- launch ----------------
extern "C" void kernel_launch(void* const* d_in, const int* in_sizes, int n_in,
                              void* d_out, int out_size) {
    const float* x     = (const float*)d_in[0];
    const int*   ei    = (const int*)d_in[1];    // int64 in reference -> delivered as int32
    const int*   batch = (const int*)d_in[2];
    const float* Wl[3]   = {(const float*)d_in[3],  (const float*)d_in[9],  (const float*)d_in[15]};
    const float* bl[3]   = {(const float*)d_in[4],  (const float*)d_in[10], (const float*)d_in[16]};
    const float* Wr[3]   = {(const float*)d_in[5],  (const float*)d_in[11], (const float*)d_in[17]};
    const float* br[3]   = {(const float*)d_in[6],  (const float*)d_in[12], (const float*)d_in[18]};
    const float* att[3]  = {(const float*)d_in[7],  (const float*)d_in[13], (const float*)d_in[19]};
    const float* bias[3] = {(const float*)d_in[8],  (const float*)d_in[14], (const float*)d_in[20]};
    const float* Wout    = (const float*)d_in[21];
    const float* bout    = (const float*)d_in[22];
    float* out = (float*)d_out;

    (void)in_sizes; (void)n_in; (void)out_size;

    k_init<<<256, 256>>>();

    int ebl = (EP + 255) / 256;
    k_deg<<<ebl, 256>>>(ei);
    k_scan<<<1, 1024>>>();
    k_scatter<<<ebl, 256>>>(ei);

    dim3 ggrid((NN + 63) / 64, HC / 64);
    int abl = (NN * 32 + 255) / 256;

    // layer 0 (K=128, no relu)
    k_dualgemm<FIN, false><<<ggrid, 256>>>(x, Wl[0], bl[0], Wr[0], br[0]);
    k_agg<<<abl, 256>>>(att[0], bias[0]);
    // layer 1 (K=256, relu on input)
    k_dualgemm<HC, true><<<ggrid, 256>>>(nullptr, Wl[1], bl[1], Wr[1], br[1]);
    k_agg<<<abl, 256>>>(att[1], bias[1]);
    // layer 2
    k_dualgemm<HC, true><<<ggrid, 256>>>(nullptr, Wl[2], bl[2], Wr[2], br[2]);
    k_agg<<<abl, 256>>>(att[2], bias[2]);

    k_cnt<<<(NN + 255) / 256, 256>>>(batch);
    k_pool<<<(NN + 255) / 256, 256>>>(batch);
    k_final<<<1, 64>>>(Wout, bout, out);
}

// round 5
// speedup vs baseline: 1.3382x; 1.3382x over previous
#include <cuda_runtime.h>
#include <cuda_bf16.h>
#include <math_constants.h>
#include <cstdint>

// Problem constants (fixed by the dataset)
#define NN   50000
#define EE   600000
#define EP   (EE + NN)     // edges + self loops = 650000
#define FIN  128
#define HC   256           // H*C = 4*64
#define NG   64            // graphs
#define NCLS 3

#define SMEM_SWIZZLE_128B(b) ((b) ^ (((b) >> 3) & 0x70))

__device__ __forceinline__ uint32_t smem_to_u32(const void* p) {
    uint32_t a;
    asm("{ .reg .u64 t; cvta.to.shared.u64 t, %1; cvt.u32.u64 %0, t; }" : "=r"(a) : "l"(p));
    return a;
}
__device__ __forceinline__ void cp_async16(uint32_t dst, const void* src, bool pred) {
    int sz = pred ? 16 : 0;
    asm volatile("cp.async.cg.shared.global [%0], [%1], 16, %2;"
                 :: "r"(dst), "l"(src), "r"(sz) : "memory");
}
__device__ __forceinline__ void ldsm_x4(uint32_t* r, uint32_t addr) {
    asm volatile("ldmatrix.sync.aligned.m8n8.x4.shared.b16 {%0,%1,%2,%3}, [%4];"
                 : "=r"(r[0]), "=r"(r[1]), "=r"(r[2]), "=r"(r[3]) : "r"(addr));
}
__device__ __forceinline__ void mma16816(float* c, const uint32_t* a, const uint32_t* b) {
    asm volatile("mma.sync.aligned.m16n8k16.row.col.f32.bf16.bf16.f32 "
                 "{%0,%1,%2,%3}, {%4,%5,%6,%7}, {%8,%9}, {%0,%1,%2,%3};"
                 : "+f"(c[0]), "+f"(c[1]), "+f"(c[2]), "+f"(c[3])
                 : "r"(a[0]), "r"(a[1]), "r"(a[2]), "r"(a[3]), "r"(b[0]), "r"(b[1]));
}

// ---------------- device scratch (no allocation allowed) ----------------
__device__ float g_XL[(size_t)NN * HC];
__device__ float g_XR[(size_t)NN * HC];
__device__ float g_H [(size_t)NN * HC];
__device__ __align__(16) __nv_bfloat16 g_Ab[(size_t)NN * 768];   // A packed [hi|lo|hi], stride 3K
__device__ __align__(16) __nv_bfloat16 g_Wb[512 * 768];          // B packed [Whi|Whi|Wlo], [n][k]
__device__ int   g_deg[NN];
__device__ int   g_off[NN];
__device__ int   g_cur[NN];
__device__ int   g_esrc[EP];
__device__ float    g_psum[NG * HC];
__device__ unsigned g_pmax[NG * HC];
__device__ int      g_cnt[NG];

__device__ __forceinline__ unsigned fkey(float f) {
    unsigned b = __float_as_uint(f);
    return (b & 0x80000000u) ? ~b : (b | 0x80000000u);
}
__device__ __forceinline__ float fdekey(unsigned u) {
    return (u & 0x80000000u) ? __uint_as_float(u & 0x7FFFFFFFu) : __uint_as_float(~u);
}

// ---------------- init ----------------
__global__ void k_init() {
    int i = blockIdx.x * blockDim.x + threadIdx.x;
    int stride = gridDim.x * blockDim.x;
    for (int j = i; j < NN; j += stride) g_deg[j] = 0;
    for (int j = i; j < NG * HC; j += stride) { g_psum[j] = 0.f; g_pmax[j] = 0x007FFFFFu; }
    for (int j = i; j < NG; j += stride) g_cnt[j] = 0;
}

// ---------------- CSR build ----------------
__global__ void k_deg(const int* __restrict__ ei) {
    int i = blockIdx.x * blockDim.x + threadIdx.x;
    if (i >= EP) return;
    int d = (i < EE) ? ei[EE + i] : (i - EE);
    atomicAdd(&g_deg[d], 1);
}

__global__ void k_scan() {
    __shared__ int wsum[32];
    __shared__ int tot;
    int tid = threadIdx.x, lane = tid & 31, wid = tid >> 5;
    int running = 0;
    for (int base = 0; base < NN; base += 1024) {
        int i = base + tid;
        int v = (i < NN) ? g_deg[i] : 0;
        int x = v;
        #pragma unroll
        for (int o = 1; o < 32; o <<= 1) {
            int t = __shfl_up_sync(0xFFFFFFFFu, x, o);
            if (lane >= o) x += t;
        }
        if (lane == 31) wsum[wid] = x;
        __syncthreads();
        if (wid == 0) {
            int orig = wsum[lane];
            int y = orig;
            #pragma unroll
            for (int o = 1; o < 32; o <<= 1) {
                int t = __shfl_up_sync(0xFFFFFFFFu, y, o);
                if (lane >= o) y += t;
            }
            wsum[lane] = y - orig;
        }
        __syncthreads();
        int incl = x + wsum[wid];
        if (i < NN) {
            int ex = running + incl - v;
            g_off[i] = ex;
            g_cur[i] = ex;
        }
        if (tid == 1023) tot = incl;
        __syncthreads();
        running += tot;
    }
}

__global__ void k_scatter(const int* __restrict__ ei) {
    int i = blockIdx.x * blockDim.x + threadIdx.x;
    if (i >= EP) return;
    int s, d;
    if (i < EE) { s = ei[i]; d = ei[EE + i]; }
    else        { s = d = i - EE; }
    int pos = atomicAdd(&g_cur[d], 1);
    g_esrc[pos] = s;
}

// ---------------- fp32 -> packed bf16 hi/lo conversions ----------------
// A packed row: [hi (K) | lo (K) | hi (K)]
// in == nullptr  ->  read from g_H (device-resolved; NEVER pass g_H from host!)
template <int K, bool RELU>
__global__ void k_convA(const float* __restrict__ in) {
    const float* src = in ? in : g_H;
    int i = blockIdx.x * blockDim.x + threadIdx.x;
    if (i >= NN * K / 4) return;
    constexpr int K4 = K / 4;
    int row = i / K4, j = (i - row * K4) * 4;
    float4 v = ((const float4*)src)[i];
    if (RELU) {
        v.x = fmaxf(v.x, 0.f); v.y = fmaxf(v.y, 0.f);
        v.z = fmaxf(v.z, 0.f); v.w = fmaxf(v.w, 0.f);
    }
    __nv_bfloat16 hx = __float2bfloat16(v.x), hy = __float2bfloat16(v.y);
    __nv_bfloat16 hz = __float2bfloat16(v.z), hw = __float2bfloat16(v.w);
    __nv_bfloat162 h01(hx, hy), h23(hz, hw);
    __nv_bfloat162 l01(__float2bfloat16(v.x - __bfloat162float(hx)),
                       __float2bfloat16(v.y - __bfloat162float(hy)));
    __nv_bfloat162 l23(__float2bfloat16(v.z - __bfloat162float(hz)),
                       __float2bfloat16(v.w - __bfloat162float(hw)));
    size_t base = (size_t)row * (3 * K);
    *(__nv_bfloat162*)&g_Ab[base + j]             = h01;
    *(__nv_bfloat162*)&g_Ab[base + j + 2]         = h23;
    *(__nv_bfloat162*)&g_Ab[base + K + j]         = l01;
    *(__nv_bfloat162*)&g_Ab[base + K + j + 2]     = l23;
    *(__nv_bfloat162*)&g_Ab[base + 2 * K + j]     = h01;
    *(__nv_bfloat162*)&g_Ab[base + 2 * K + j + 2] = h23;
}

// W: [K][256] fp32 row-major -> g_Wb[n][k'] = [Whi | Whi | Wlo], n-major
__global__ void k_convW(const float* __restrict__ W, int K, int nbase) {
    int i = blockIdx.x * blockDim.x + threadIdx.x;
    if (i >= K * 256) return;
    int k = i >> 8, n = i & 255;
    float v = W[i];
    __nv_bfloat16 h = __float2bfloat16(v);
    __nv_bfloat16 l = __float2bfloat16(v - __bfloat162float(h));
    size_t base = (size_t)(nbase + n) * (3 * K);
    g_Wb[base + k]         = h;
    g_Wb[base + K + k]     = h;
    g_Wb[base + 2 * K + k] = l;
}

// ---------------- mma.sync bf16 GEMM ----------------
// C[128 x 128] per CTA of the NN x 512 output (cols 0..255 -> XL, 256..511 -> XR).
// A: g_Ab [NN][KTOT], B: g_Wb [n][KTOT] (n-major, K contiguous).
#define TILE_BYTES (128 * 64 * 2)   // one buffer: 128 rows x 64 bf16 = 16KB

template <int KTOT>
__global__ void __launch_bounds__(256, 1) k_gemm(const float* __restrict__ biasL,
                                                 const float* __restrict__ biasR) {
    extern __shared__ char smem[];
    const int tid = threadIdx.x;
    const int lane = tid & 31, wid = tid >> 5;
    const int m0 = blockIdx.x * 128;
    const int n0 = blockIdx.y * 128;
    const int wm = (wid & 3) * 32;
    const int wn = (wid >> 2) * 64;

    uint32_t sbase = smem_to_u32(smem);
    // layout: A0 A1 B0 B1, 16KB each
    uint32_t sA0 = sbase, sB0 = sbase + 2 * TILE_BYTES;

    float acc[2][8][4];
    #pragma unroll
    for (int mt = 0; mt < 2; mt++)
        #pragma unroll
        for (int nt = 0; nt < 8; nt++)
            #pragma unroll
            for (int q = 0; q < 4; q++) acc[mt][nt][q] = 0.f;

    constexpr int NT = KTOT / 64;

    auto issue = [&](int buf, int k0) {
        uint32_t ab = sA0 + buf * TILE_BYTES;
        uint32_t bb = sB0 + buf * TILE_BYTES;
        #pragma unroll
        for (int i = 0; i < 4; i++) {
            int chunk = tid + i * 256;          // 0..1023
            int row = chunk >> 3, seg = chunk & 7;
            int sw = SMEM_SWIZZLE_128B(row * 128 + seg * 16);
            bool ok = (m0 + row) < NN;
            int grow = ok ? (m0 + row) : 0;
            cp_async16(ab + sw, &g_Ab[(size_t)grow * KTOT + k0 + seg * 8], ok);
        }
        #pragma unroll
        for (int i = 0; i < 4; i++) {
            int chunk = tid + i * 256;
            int row = chunk >> 3, seg = chunk & 7;
            int sw = SMEM_SWIZZLE_128B(row * 128 + seg * 16);
            cp_async16(bb + sw, &g_Wb[(size_t)(n0 + row) * KTOT + k0 + seg * 8], true);
        }
        asm volatile("cp.async.commit_group;" ::: "memory");
    };

    issue(0, 0);

    for (int t = 0; t < NT; t++) {
        int buf = t & 1;
        if (t + 1 < NT) {
            issue(buf ^ 1, (t + 1) * 64);
            asm volatile("cp.async.wait_group 1;" ::: "memory");
        } else {
            asm volatile("cp.async.wait_group 0;" ::: "memory");
        }
        __syncthreads();

        uint32_t ab = sA0 + buf * TILE_BYTES;
        uint32_t bb = sB0 + buf * TILE_BYTES;
        #pragma unroll
        for (int ks = 0; ks < 4; ks++) {
            int k16 = ks * 16;
            uint32_t a[2][4];
            #pragma unroll
            for (int mt = 0; mt < 2; mt++) {
                int row = wm + mt * 16 + (lane & 15);
                int col = k16 + (lane >> 4) * 8;
                ldsm_x4(a[mt], ab + SMEM_SWIZZLE_128B(row * 128 + col * 2));
            }
            uint32_t b[4][4];
            #pragma unroll
            for (int nt = 0; nt < 4; nt++) {
                int row = wn + nt * 16 + (lane & 7) + ((lane >> 4) << 3);
                int col = k16 + ((lane >> 3) & 1) * 8;
                ldsm_x4(b[nt], bb + SMEM_SWIZZLE_128B(row * 128 + col * 2));
            }
            #pragma unroll
            for (int mt = 0; mt < 2; mt++)
                #pragma unroll
                for (int nt = 0; nt < 8; nt++)
                    mma16816(acc[mt][nt], a[mt], &b[nt >> 1][(nt & 1) * 2]);
        }
        __syncthreads();
    }

    // epilogue: bias add + split XL/XR
    bool halfR = (n0 + wn) >= 256;
    float* outp = halfR ? g_XR : g_XL;
    const float* bias = halfR ? biasR : biasL;
    int cb = n0 + wn - (halfR ? 256 : 0);
    #pragma unroll
    for (int mt = 0; mt < 2; mt++) {
        int r0 = m0 + wm + mt * 16 + (lane >> 2);
        #pragma unroll
        for (int nt = 0; nt < 8; nt++) {
            int c = cb + nt * 8 + (lane & 3) * 2;
            float b0 = bias[c], b1 = bias[c + 1];
            if (r0 < NN)
                *(float2*)&outp[(size_t)r0 * HC + c] =
                    make_float2(acc[mt][nt][0] + b0, acc[mt][nt][1] + b1);
            if (r0 + 8 < NN)
                *(float2*)&outp[(size_t)(r0 + 8) * HC + c] =
                    make_float2(acc[mt][nt][2] + b0, acc[mt][nt][3] + b1);
        }
    }
}

// ---------------- warp-per-node edge softmax + aggregation ----------------
__global__ void k_agg(const float* __restrict__ att, const float* __restrict__ bias) {
    int gt = blockIdx.x * blockDim.x + threadIdx.x;
    int node = gt >> 5;
    int lane = gt & 31;
    if (node >= NN) return;

    int fb = lane * 8;

    float4 x0 = *(const float4*)&g_XR[(size_t)node * HC + fb];
    float4 x1 = *(const float4*)&g_XR[(size_t)node * HC + fb + 4];
    float xr[8] = {x0.x, x0.y, x0.z, x0.w, x1.x, x1.y, x1.z, x1.w};
    float4 a0 = *(const float4*)&att[fb];
    float4 a1 = *(const float4*)&att[fb + 4];
    float at[8] = {a0.x, a0.y, a0.z, a0.w, a1.x, a1.y, a1.z, a1.w};

    float acc[8];
    #pragma unroll
    for (int j = 0; j < 8; j++) acc[j] = 0.f;
    float m = -CUDART_INF_F, den = 0.f;

    int st = g_off[node];
    int en = st + g_deg[node];

    for (int e = st; e < en; e++) {
        int s = g_esrc[e];
        float4 v0 = *(const float4*)&g_XL[(size_t)s * HC + fb];
        float4 v1 = *(const float4*)&g_XL[(size_t)s * HC + fb + 4];
        float v[8] = {v0.x, v0.y, v0.z, v0.w, v1.x, v1.y, v1.z, v1.w};

        float ps = 0.f;
        #pragma unroll
        for (int j = 0; j < 8; j++) {
            float t = v[j] + xr[j];
            t = (t > 0.f) ? t : 0.2f * t;
            ps = fmaf(t, at[j], ps);
        }
        ps += __shfl_xor_sync(0xFFFFFFFFu, ps, 1);
        ps += __shfl_xor_sync(0xFFFFFFFFu, ps, 2);
        ps += __shfl_xor_sync(0xFFFFFFFFu, ps, 4);

        float mn = fmaxf(m, ps);
        float scale = __expf(m - mn);
        float w = __expf(ps - mn);
        den = den * scale + w;
        #pragma unroll
        for (int j = 0; j < 8; j++) acc[j] = fmaf(acc[j], scale, w * v[j]);
        m = mn;
    }

    float inv = 1.f / den;
    float4 bb0 = *(const float4*)&bias[fb];
    float4 bb1 = *(const float4*)&bias[fb + 4];
    float bs[8] = {bb0.x, bb0.y, bb0.z, bb0.w, bb1.x, bb1.y, bb1.z, bb1.w};
    float4 o0 = make_float4(acc[0] * inv + bs[0], acc[1] * inv + bs[1],
                            acc[2] * inv + bs[2], acc[3] * inv + bs[3]);
    float4 o1 = make_float4(acc[4] * inv + bs[4], acc[5] * inv + bs[5],
                            acc[6] * inv + bs[6], acc[7] * inv + bs[7]);
    *(float4*)&g_H[(size_t)node * HC + fb]     = o0;
    *(float4*)&g_H[(size_t)node * HC + fb + 4] = o1;
}

// ---------------- pooling ----------------
__global__ void k_cnt(const int* __restrict__ batch) {
    int i = blockIdx.x * blockDim.x + threadIdx.x;
    if (i < NN) atomicAdd(&g_cnt[batch[i]], 1);
}

__global__ void k_pool(const int* __restrict__ batch) {
    int f = threadIdx.x;
    int n0 = blockIdx.x * 256;
    int n1 = min(n0 + 256, NN);
    int curg = -1;
    float s = 0.f, mx = -CUDART_INF_F;
    for (int n = n0; n < n1; n++) {
        int g = batch[n];
        float v = g_H[(size_t)n * HC + f];
        if (g != curg) {
            if (curg >= 0) {
                atomicAdd(&g_psum[curg * HC + f], s);
                atomicMax(&g_pmax[curg * HC + f], fkey(mx));
            }
            curg = g; s = 0.f; mx = -CUDART_INF_F;
        }
        s += v;
        mx = fmaxf(mx, v);
    }
    if (curg >= 0) {
        atomicAdd(&g_psum[curg * HC + f], s);
        atomicMax(&g_pmax[curg * HC + f], fkey(mx));
    }
}

// ---------------- classifier + softmax ----------------
__global__ void k_final(const float* __restrict__ Wout, const float* __restrict__ bout,
                        float* __restrict__ out) {
    int g = threadIdx.x;
    if (g >= NG) return;
    float c = (float)max(g_cnt[g], 1);
    float inv_c = 1.f / c;
    float l0 = bout[0], l1 = bout[1], l2 = bout[2];
    for (int f = 0; f < HC; f++) {
        float p = g_psum[g * HC + f] * inv_c + fdekey(g_pmax[g * HC + f]);
        l0 = fmaf(p, Wout[f * NCLS + 0], l0);
        l1 = fmaf(p, Wout[f * NCLS + 1], l1);
        l2 = fmaf(p, Wout[f * NCLS + 2], l2);
    }
    float mx = fmaxf(l0, fmaxf(l1, l2));
    float e0 = __expf(l0 - mx), e1 = __expf(l1 - mx), e2 = __expf(l2 - mx);
    float inv = 1.f / (e0 + e1 + e2);
    out[g * NCLS + 0] = e0 * inv;
    out[g * NCLS + 1] = e1 * inv;
    out[g * NCLS + 2] = e2 * inv;
}

// ---------------- launch ----------------
extern "C" void kernel_launch(void* const* d_in, const int* in_sizes, int n_in,
                              void* d_out, int out_size) {
    const float* x     = (const float*)d_in[0];
    const int*   ei    = (const int*)d_in[1];
    const int*   batch = (const int*)d_in[2];
    const float* Wl[3]   = {(const float*)d_in[3],  (const float*)d_in[9],  (const float*)d_in[15]};
    const float* bl[3]   = {(const float*)d_in[4],  (const float*)d_in[10], (const float*)d_in[16]};
    const float* Wr[3]   = {(const float*)d_in[5],  (const float*)d_in[11], (const float*)d_in[17]};
    const float* br[3]   = {(const float*)d_in[6],  (const float*)d_in[12], (const float*)d_in[18]};
    const float* att[3]  = {(const float*)d_in[7],  (const float*)d_in[13], (const float*)d_in[19]};
    const float* bias[3] = {(const float*)d_in[8],  (const float*)d_in[14], (const float*)d_in[20]};
    const float* Wout    = (const float*)d_in[21];
    const float* bout    = (const float*)d_in[22];
    float* out = (float*)d_out;

    (void)in_sizes; (void)n_in; (void)out_size;

    static bool attr_done = false;
    if (!attr_done) {
        cudaFuncSetAttribute(k_gemm<384>, cudaFuncAttributeMaxDynamicSharedMemorySize, 4 * TILE_BYTES);
        cudaFuncSetAttribute(k_gemm<768>, cudaFuncAttributeMaxDynamicSharedMemorySize, 4 * TILE_BYTES);
        attr_done = true;
    }

    k_init<<<256, 256>>>();

    int ebl = (EP + 255) / 256;
    k_deg<<<ebl, 256>>>(ei);
    k_scan<<<1, 1024>>>();
    k_scatter<<<ebl, 256>>>(ei);

    dim3 ggrid((NN + 127) / 128, 4);
    int abl = (NN * 32 + 255) / 256;
    int wblocks = (256 * 256 + 255) / 256;

    // layer 0 (K=128)
    k_convA<FIN, false><<<(NN * FIN / 4 + 255) / 256, 256>>>(x);
    k_convW<<<(FIN * 256 + 255) / 256, 256>>>(Wl[0], FIN, 0);
    k_convW<<<(FIN * 256 + 255) / 256, 256>>>(Wr[0], FIN, 256);
    k_gemm<384><<<ggrid, 256, 4 * TILE_BYTES>>>(bl[0], br[0]);
    k_agg<<<abl, 256>>>(att[0], bias[0]);

    // layers 1,2 (K=256, relu on input, input = g_H resolved on device)
    for (int li = 1; li < 3; li++) {
        k_convA<HC, true><<<(NN * HC / 4 + 255) / 256, 256>>>(nullptr);
        k_convW<<<wblocks, 256>>>(Wl[li], HC, 0);
        k_convW<<<wblocks, 256>>>(Wr[li], HC, 256);
        k_gemm<768><<<ggrid, 256, 4 * TILE_BYTES>>>(bl[li], br[li]);
        k_agg<<<abl, 256>>>(att[li], bias[li]);
    }

    k_cnt<<<(NN + 255) / 256, 256>>>(batch);
    k_pool<<<(NN + 255) / 256, 256>>>(batch);
    k_final<<<1, 64>>>(Wout, bout, out);
}

// round 6
// speedup vs baseline: 1.4641x; 1.0941x over previous
#include <cuda_runtime.h>
#include <cuda_bf16.h>
#include <math_constants.h>
#include <cstdint>

// Problem constants (fixed by the dataset)
#define NN   50000
#define EE   600000
#define EP   (EE + NN)     // edges + self loops = 650000
#define FIN  128
#define HC   256           // H*C = 4*64
#define NG   64            // graphs
#define NCLS 3

#define SMEM_SWIZZLE_128B(b) ((b) ^ (((b) >> 3) & 0x70))

__device__ __forceinline__ uint32_t smem_to_u32(const void* p) {
    uint32_t a;
    asm("{ .reg .u64 t; cvta.to.shared.u64 t, %1; cvt.u32.u64 %0, t; }" : "=r"(a) : "l"(p));
    return a;
}
__device__ __forceinline__ void cp_async16(uint32_t dst, const void* src, bool pred) {
    int sz = pred ? 16 : 0;
    asm volatile("cp.async.cg.shared.global [%0], [%1], 16, %2;"
                 :: "r"(dst), "l"(src), "r"(sz) : "memory");
}
template <int N>
__device__ __forceinline__ void cp_async_wait() {
    asm volatile("cp.async.wait_group %0;" :: "n"(N) : "memory");
}
__device__ __forceinline__ void ldsm_x4(uint32_t* r, uint32_t addr) {
    asm volatile("ldmatrix.sync.aligned.m8n8.x4.shared.b16 {%0,%1,%2,%3}, [%4];"
                 : "=r"(r[0]), "=r"(r[1]), "=r"(r[2]), "=r"(r[3]) : "r"(addr));
}
__device__ __forceinline__ void mma16816(float* c, const uint32_t* a, const uint32_t* b) {
    asm volatile("mma.sync.aligned.m16n8k16.row.col.f32.bf16.bf16.f32 "
                 "{%0,%1,%2,%3}, {%4,%5,%6,%7}, {%8,%9}, {%0,%1,%2,%3};"
                 : "+f"(c[0]), "+f"(c[1]), "+f"(c[2]), "+f"(c[3])
                 : "r"(a[0]), "r"(a[1]), "r"(a[2]), "r"(a[3]), "r"(b[0]), "r"(b[1]));
}

// ---------------- device scratch (no allocation allowed) ----------------
__device__ float g_XL[(size_t)NN * HC];
__device__ float g_XR[(size_t)NN * HC];
__device__ float g_H [(size_t)NN * HC];
__device__ __align__(16) __nv_bfloat16 g_Ab[(size_t)NN * 768];   // A packed [hi|lo|hi], stride 3K
__device__ __align__(16) __nv_bfloat16 g_Wb[512 * 768];          // B packed [Whi|Whi|Wlo], [n][k]
__device__ int   g_deg[NN];
__device__ int   g_off[NN];
__device__ int   g_cur[NN];
__device__ int   g_esrc[EP];
__device__ float    g_psum[NG * HC];
__device__ unsigned g_pmax[NG * HC];
__device__ int      g_cnt[NG];

__device__ __forceinline__ unsigned fkey(float f) {
    unsigned b = __float_as_uint(f);
    return (b & 0x80000000u) ? ~b : (b | 0x80000000u);
}
__device__ __forceinline__ float fdekey(unsigned u) {
    return (u & 0x80000000u) ? __uint_as_float(u & 0x7FFFFFFFu) : __uint_as_float(~u);
}

// ---------------- init ----------------
__global__ void k_init() {
    int i = blockIdx.x * blockDim.x + threadIdx.x;
    int stride = gridDim.x * blockDim.x;
    for (int j = i; j < NN; j += stride) g_deg[j] = 0;
    for (int j = i; j < NG * HC; j += stride) { g_psum[j] = 0.f; g_pmax[j] = 0x007FFFFFu; }
    for (int j = i; j < NG; j += stride) g_cnt[j] = 0;
}

// ---------------- CSR build ----------------
__global__ void k_deg(const int* __restrict__ ei) {
    int i = blockIdx.x * blockDim.x + threadIdx.x;
    if (i >= EP) return;
    int d = (i < EE) ? ei[EE + i] : (i - EE);
    atomicAdd(&g_deg[d], 1);
}

__global__ void k_scan() {
    __shared__ int wsum[32];
    __shared__ int tot;
    int tid = threadIdx.x, lane = tid & 31, wid = tid >> 5;
    int running = 0;
    for (int base = 0; base < NN; base += 1024) {
        int i = base + tid;
        int v = (i < NN) ? g_deg[i] : 0;
        int x = v;
        #pragma unroll
        for (int o = 1; o < 32; o <<= 1) {
            int t = __shfl_up_sync(0xFFFFFFFFu, x, o);
            if (lane >= o) x += t;
        }
        if (lane == 31) wsum[wid] = x;
        __syncthreads();
        if (wid == 0) {
            int orig = wsum[lane];
            int y = orig;
            #pragma unroll
            for (int o = 1; o < 32; o <<= 1) {
                int t = __shfl_up_sync(0xFFFFFFFFu, y, o);
                if (lane >= o) y += t;
            }
            wsum[lane] = y - orig;
        }
        __syncthreads();
        int incl = x + wsum[wid];
        if (i < NN) {
            int ex = running + incl - v;
            g_off[i] = ex;
            g_cur[i] = ex;
        }
        if (tid == 1023) tot = incl;
        __syncthreads();
        running += tot;
    }
}

__global__ void k_scatter(const int* __restrict__ ei) {
    int i = blockIdx.x * blockDim.x + threadIdx.x;
    if (i >= EP) return;
    int s, d;
    if (i < EE) { s = ei[i]; d = ei[EE + i]; }
    else        { s = d = i - EE; }
    int pos = atomicAdd(&g_cur[d], 1);
    g_esrc[pos] = s;
}

// ---------------- fp32 -> packed bf16 hi/lo (layer 0 input only) ----------------
template <int K, bool RELU>
__global__ void k_convA(const float* __restrict__ in) {
    const float* src = in ? in : g_H;
    int i = blockIdx.x * blockDim.x + threadIdx.x;
    if (i >= NN * K / 4) return;
    constexpr int K4 = K / 4;
    int row = i / K4, j = (i - row * K4) * 4;
    float4 v = ((const float4*)src)[i];
    if (RELU) {
        v.x = fmaxf(v.x, 0.f); v.y = fmaxf(v.y, 0.f);
        v.z = fmaxf(v.z, 0.f); v.w = fmaxf(v.w, 0.f);
    }
    __nv_bfloat16 hx = __float2bfloat16(v.x), hy = __float2bfloat16(v.y);
    __nv_bfloat16 hz = __float2bfloat16(v.z), hw = __float2bfloat16(v.w);
    __nv_bfloat162 h01(hx, hy), h23(hz, hw);
    __nv_bfloat162 l01(__float2bfloat16(v.x - __bfloat162float(hx)),
                       __float2bfloat16(v.y - __bfloat162float(hy)));
    __nv_bfloat162 l23(__float2bfloat16(v.z - __bfloat162float(hz)),
                       __float2bfloat16(v.w - __bfloat162float(hw)));
    size_t base = (size_t)row * (3 * K);
    *(__nv_bfloat162*)&g_Ab[base + j]             = h01;
    *(__nv_bfloat162*)&g_Ab[base + j + 2]         = h23;
    *(__nv_bfloat162*)&g_Ab[base + K + j]         = l01;
    *(__nv_bfloat162*)&g_Ab[base + K + j + 2]     = l23;
    *(__nv_bfloat162*)&g_Ab[base + 2 * K + j]     = h01;
    *(__nv_bfloat162*)&g_Ab[base + 2 * K + j + 2] = h23;
}

// W: [K][256] fp32 row-major -> g_Wb[n][k'] = [Whi | Whi | Wlo], n-major
__global__ void k_convW(const float* __restrict__ W, int K, int nbase) {
    int i = blockIdx.x * blockDim.x + threadIdx.x;
    if (i >= K * 256) return;
    int k = i >> 8, n = i & 255;
    float v = W[i];
    __nv_bfloat16 h = __float2bfloat16(v);
    __nv_bfloat16 l = __float2bfloat16(v - __bfloat162float(h));
    size_t base = (size_t)(nbase + n) * (3 * K);
    g_Wb[base + k]         = h;
    g_Wb[base + K + k]     = h;
    g_Wb[base + 2 * K + k] = l;
}

// ---------------- mma.sync bf16 GEMM v2 ----------------
// CTA tile 128 x 256 of the NN x 512 output. 512 threads = 16 warps (4M x 4N).
// 3-stage cp.async pipeline, K-chunk 64 (128B rows, SW128 swizzle).
#define A_BYTES (128 * 64 * 2)   // 16KB
#define B_BYTES (256 * 64 * 2)   // 32KB
#define GEMM_SMEM (3 * (A_BYTES + B_BYTES))   // 144KB

template <int KTOT>
__global__ void __launch_bounds__(512, 1) k_gemm(const float* __restrict__ biasL,
                                                 const float* __restrict__ biasR) {
    extern __shared__ char smem[];
    const int tid = threadIdx.x;
    const int lane = tid & 31, wid = tid >> 5;
    const int m0 = blockIdx.x * 128;
    const int n0 = blockIdx.y * 256;
    const int wm = (wid & 3) * 32;
    const int wn = (wid >> 2) * 64;

    uint32_t sbase = smem_to_u32(smem);

    float acc[2][8][4];
    #pragma unroll
    for (int mt = 0; mt < 2; mt++)
        #pragma unroll
        for (int nt = 0; nt < 8; nt++)
            #pragma unroll
            for (int q = 0; q < 4; q++) acc[mt][nt][q] = 0.f;

    constexpr int NT = KTOT / 64;

    auto issue = [&](int slot, int k0) {
        uint32_t ab = sbase + slot * A_BYTES;
        uint32_t bb = sbase + 3 * A_BYTES + slot * B_BYTES;
        #pragma unroll
        for (int i = 0; i < 2; i++) {           // A: 1024 16B-chunks
            int chunk = tid + i * 512;
            int row = chunk >> 3, seg = chunk & 7;
            int sw = SMEM_SWIZZLE_128B(row * 128 + seg * 16);
            bool ok = (m0 + row) < NN;
            int grow = ok ? (m0 + row) : 0;
            cp_async16(ab + sw, &g_Ab[(size_t)grow * KTOT + k0 + seg * 8], ok);
        }
        #pragma unroll
        for (int i = 0; i < 4; i++) {           // B: 2048 16B-chunks
            int chunk = tid + i * 512;
            int row = chunk >> 3, seg = chunk & 7;
            int sw = SMEM_SWIZZLE_128B(row * 128 + seg * 16);
            cp_async16(bb + sw, &g_Wb[(size_t)(n0 + row) * KTOT + k0 + seg * 8], true);
        }
        asm volatile("cp.async.commit_group;" ::: "memory");
    };

    issue(0, 0);
    issue(1, 64);

    for (int t = 0; t < NT; t++) {
        if (t + 1 < NT) cp_async_wait<1>(); else cp_async_wait<0>();
        __syncthreads();
        if (t + 2 < NT) issue((t + 2) % 3, (t + 2) * 64);

        int slot = t % 3;
        uint32_t ab = sbase + slot * A_BYTES;
        uint32_t bb = sbase + 3 * A_BYTES + slot * B_BYTES;
        #pragma unroll
        for (int ks = 0; ks < 4; ks++) {
            int k16 = ks * 16;
            uint32_t a[2][4];
            #pragma unroll
            for (int mt = 0; mt < 2; mt++) {
                int row = wm + mt * 16 + (lane & 15);
                int col = k16 + (lane >> 4) * 8;
                ldsm_x4(a[mt], ab + SMEM_SWIZZLE_128B(row * 128 + col * 2));
            }
            uint32_t b[4][4];
            #pragma unroll
            for (int nt = 0; nt < 4; nt++) {
                int row = wn + nt * 16 + (lane & 7) + ((lane >> 4) << 3);
                int col = k16 + ((lane >> 3) & 1) * 8;
                ldsm_x4(b[nt], bb + SMEM_SWIZZLE_128B(row * 128 + col * 2));
            }
            #pragma unroll
            for (int mt = 0; mt < 2; mt++)
                #pragma unroll
                for (int nt = 0; nt < 8; nt++)
                    mma16816(acc[mt][nt], a[mt], &b[nt >> 1][(nt & 1) * 2]);
        }
    }

    // epilogue: bias add + split XL/XR
    bool halfR = (n0 + wn) >= 256;
    float* outp = halfR ? g_XR : g_XL;
    const float* bias = halfR ? biasR : biasL;
    int cb = n0 + wn - (halfR ? 256 : 0);
    #pragma unroll
    for (int mt = 0; mt < 2; mt++) {
        int r0 = m0 + wm + mt * 16 + (lane >> 2);
        #pragma unroll
        for (int nt = 0; nt < 8; nt++) {
            int c = cb + nt * 8 + (lane & 3) * 2;
            float b0 = bias[c], b1 = bias[c + 1];
            if (r0 < NN)
                *(float2*)&outp[(size_t)r0 * HC + c] =
                    make_float2(acc[mt][nt][0] + b0, acc[mt][nt][1] + b1);
            if (r0 + 8 < NN)
                *(float2*)&outp[(size_t)(r0 + 8) * HC + c] =
                    make_float2(acc[mt][nt][2] + b0, acc[mt][nt][3] + b1);
        }
    }
}

// ---------------- warp-per-node edge softmax + aggregation ----------------
// PACK=true: write relu(h) as bf16 [hi|lo|hi] (stride 768) directly to g_Ab (feeds next GEMM).
// PACK=false: write h (fp32) to g_H (feeds pooling).
template <bool PACK>
__global__ void k_agg(const float* __restrict__ att, const float* __restrict__ bias) {
    int gt = blockIdx.x * blockDim.x + threadIdx.x;
    int node = gt >> 5;
    int lane = gt & 31;
    if (node >= NN) return;

    int fb = lane * 8;

    float4 x0 = *(const float4*)&g_XR[(size_t)node * HC + fb];
    float4 x1 = *(const float4*)&g_XR[(size_t)node * HC + fb + 4];
    float xr[8] = {x0.x, x0.y, x0.z, x0.w, x1.x, x1.y, x1.z, x1.w};
    float4 a0 = *(const float4*)&att[fb];
    float4 a1 = *(const float4*)&att[fb + 4];
    float at[8] = {a0.x, a0.y, a0.z, a0.w, a1.x, a1.y, a1.z, a1.w};

    float acc[8];
    #pragma unroll
    for (int j = 0; j < 8; j++) acc[j] = 0.f;
    float m = -CUDART_INF_F, den = 0.f;

    int st = g_off[node];
    int en = st + g_deg[node];

    int e = st;
    for (; e + 1 < en; e += 2) {
        int s0 = g_esrc[e];
        int s1 = g_esrc[e + 1];
        float4 u0 = *(const float4*)&g_XL[(size_t)s0 * HC + fb];
        float4 u1 = *(const float4*)&g_XL[(size_t)s0 * HC + fb + 4];
        float4 w0v = *(const float4*)&g_XL[(size_t)s1 * HC + fb];
        float4 w1v = *(const float4*)&g_XL[(size_t)s1 * HC + fb + 4];
        float v0[8] = {u0.x, u0.y, u0.z, u0.w, u1.x, u1.y, u1.z, u1.w};
        float v1[8] = {w0v.x, w0v.y, w0v.z, w0v.w, w1v.x, w1v.y, w1v.z, w1v.w};

        float p0 = 0.f, p1 = 0.f;
        #pragma unroll
        for (int j = 0; j < 8; j++) {
            float t0 = v0[j] + xr[j];
            float t1 = v1[j] + xr[j];
            t0 = (t0 > 0.f) ? t0 : 0.2f * t0;
            t1 = (t1 > 0.f) ? t1 : 0.2f * t1;
            p0 = fmaf(t0, at[j], p0);
            p1 = fmaf(t1, at[j], p1);
        }
        #pragma unroll
        for (int o = 1; o <= 4; o <<= 1) {
            p0 += __shfl_xor_sync(0xFFFFFFFFu, p0, o);
            p1 += __shfl_xor_sync(0xFFFFFFFFu, p1, o);
        }

        float mn = fmaxf(m, fmaxf(p0, p1));
        float sc = __expf(m - mn);
        float w0 = __expf(p0 - mn);
        float w1 = __expf(p1 - mn);
        den = fmaf(den, sc, w0 + w1);
        #pragma unroll
        for (int j = 0; j < 8; j++)
            acc[j] = fmaf(acc[j], sc, fmaf(w0, v0[j], w1 * v1[j]));
        m = mn;
    }
    if (e < en) {
        int s = g_esrc[e];
        float4 u0 = *(const float4*)&g_XL[(size_t)s * HC + fb];
        float4 u1 = *(const float4*)&g_XL[(size_t)s * HC + fb + 4];
        float v[8] = {u0.x, u0.y, u0.z, u0.w, u1.x, u1.y, u1.z, u1.w};
        float ps = 0.f;
        #pragma unroll
        for (int j = 0; j < 8; j++) {
            float t = v[j] + xr[j];
            t = (t > 0.f) ? t : 0.2f * t;
            ps = fmaf(t, at[j], ps);
        }
        #pragma unroll
        for (int o = 1; o <= 4; o <<= 1)
            ps += __shfl_xor_sync(0xFFFFFFFFu, ps, o);
        float mn = fmaxf(m, ps);
        float sc = __expf(m - mn);
        float w = __expf(ps - mn);
        den = fmaf(den, sc, w);
        #pragma unroll
        for (int j = 0; j < 8; j++) acc[j] = fmaf(acc[j], sc, w * v[j]);
        m = mn;
    }

    float inv = 1.f / den;
    float4 bb0 = *(const float4*)&bias[fb];
    float4 bb1 = *(const float4*)&bias[fb + 4];
    float bs[8] = {bb0.x, bb0.y, bb0.z, bb0.w, bb1.x, bb1.y, bb1.z, bb1.w};
    float o[8];
    #pragma unroll
    for (int j = 0; j < 8; j++) o[j] = fmaf(acc[j], inv, bs[j]);

    if (PACK) {
        // relu + hi/lo split, packed [hi | lo | hi] with K=256
        uint32_t hw[4], lw[4];
        #pragma unroll
        for (int i = 0; i < 4; i++) {
            float r0 = fmaxf(o[2 * i], 0.f);
            float r1 = fmaxf(o[2 * i + 1], 0.f);
            __nv_bfloat16 h0 = __float2bfloat16(r0);
            __nv_bfloat16 h1 = __float2bfloat16(r1);
            __nv_bfloat16 l0 = __float2bfloat16(r0 - __bfloat162float(h0));
            __nv_bfloat16 l1 = __float2bfloat16(r1 - __bfloat162float(h1));
            hw[i] = (uint32_t)__bfloat16_as_ushort(h0) |
                    ((uint32_t)__bfloat16_as_ushort(h1) << 16);
            lw[i] = (uint32_t)__bfloat16_as_ushort(l0) |
                    ((uint32_t)__bfloat16_as_ushort(l1) << 16);
        }
        size_t base = (size_t)node * 768 + fb;
        *(uint4*)&g_Ab[base]       = make_uint4(hw[0], hw[1], hw[2], hw[3]);
        *(uint4*)&g_Ab[base + 256] = make_uint4(lw[0], lw[1], lw[2], lw[3]);
        *(uint4*)&g_Ab[base + 512] = make_uint4(hw[0], hw[1], hw[2], hw[3]);
    } else {
        *(float4*)&g_H[(size_t)node * HC + fb] =
            make_float4(o[0], o[1], o[2], o[3]);
        *(float4*)&g_H[(size_t)node * HC + fb + 4] =
            make_float4(o[4], o[5], o[6], o[7]);
    }
}

// ---------------- pooling ----------------
__global__ void k_cnt(const int* __restrict__ batch) {
    int i = blockIdx.x * blockDim.x + threadIdx.x;
    if (i < NN) atomicAdd(&g_cnt[batch[i]], 1);
}

__global__ void k_pool(const int* __restrict__ batch) {
    int f = threadIdx.x;
    int n0 = blockIdx.x * 256;
    int n1 = min(n0 + 256, NN);
    int curg = -1;
    float s = 0.f, mx = -CUDART_INF_F;
    for (int n = n0; n < n1; n++) {
        int g = batch[n];
        float v = g_H[(size_t)n * HC + f];
        if (g != curg) {
            if (curg >= 0) {
                atomicAdd(&g_psum[curg * HC + f], s);
                atomicMax(&g_pmax[curg * HC + f], fkey(mx));
            }
            curg = g; s = 0.f; mx = -CUDART_INF_F;
        }
        s += v;
        mx = fmaxf(mx, v);
    }
    if (curg >= 0) {
        atomicAdd(&g_psum[curg * HC + f], s);
        atomicMax(&g_pmax[curg * HC + f], fkey(mx));
    }
}

// ---------------- classifier + softmax ----------------
__global__ void k_final(const float* __restrict__ Wout, const float* __restrict__ bout,
                        float* __restrict__ out) {
    int g = threadIdx.x;
    if (g >= NG) return;
    float c = (float)max(g_cnt[g], 1);
    float inv_c = 1.f / c;
    float l0 = bout[0], l1 = bout[1], l2 = bout[2];
    for (int f = 0; f < HC; f++) {
        float p = g_psum[g * HC + f] * inv_c + fdekey(g_pmax[g * HC + f]);
        l0 = fmaf(p, Wout[f * NCLS + 0], l0);
        l1 = fmaf(p, Wout[f * NCLS + 1], l1);
        l2 = fmaf(p, Wout[f * NCLS + 2], l2);
    }
    float mx = fmaxf(l0, fmaxf(l1, l2));
    float e0 = __expf(l0 - mx), e1 = __expf(l1 - mx), e2 = __expf(l2 - mx);
    float inv = 1.f / (e0 + e1 + e2);
    out[g * NCLS + 0] = e0 * inv;
    out[g * NCLS + 1] = e1 * inv;
    out[g * NCLS + 2] = e2 * inv;
}

// ---------------- launch ----------------
extern "C" void kernel_launch(void* const* d_in, const int* in_sizes, int n_in,
                              void* d_out, int out_size) {
    const float* x     = (const float*)d_in[0];
    const int*   ei    = (const int*)d_in[1];
    const int*   batch = (const int*)d_in[2];
    const float* Wl[3]   = {(const float*)d_in[3],  (const float*)d_in[9],  (const float*)d_in[15]};
    const float* bl[3]   = {(const float*)d_in[4],  (const float*)d_in[10], (const float*)d_in[16]};
    const float* Wr[3]   = {(const float*)d_in[5],  (const float*)d_in[11], (const float*)d_in[17]};
    const float* br[3]   = {(const float*)d_in[6],  (const float*)d_in[12], (const float*)d_in[18]};
    const float* att[3]  = {(const float*)d_in[7],  (const float*)d_in[13], (const float*)d_in[19]};
    const float* bias[3] = {(const float*)d_in[8],  (const float*)d_in[14], (const float*)d_in[20]};
    const float* Wout    = (const float*)d_in[21];
    const float* bout    = (const float*)d_in[22];
    float* out = (float*)d_out;

    (void)in_sizes; (void)n_in; (void)out_size;

    static bool attr_done = false;
    if (!attr_done) {
        cudaFuncSetAttribute(k_gemm<384>, cudaFuncAttributeMaxDynamicSharedMemorySize, GEMM_SMEM);
        cudaFuncSetAttribute(k_gemm<768>, cudaFuncAttributeMaxDynamicSharedMemorySize, GEMM_SMEM);
        attr_done = true;
    }

    k_init<<<256, 256>>>();

    int ebl = (EP + 255) / 256;
    k_deg<<<ebl, 256>>>(ei);
    k_scan<<<1, 1024>>>();
    k_scatter<<<ebl, 256>>>(ei);

    dim3 ggrid((NN + 127) / 128, 2);
    int abl = (NN * 32 + 255) / 256;
    int wblocks = (256 * 256 + 255) / 256;

    // layer 0 (K=128)
    k_convA<FIN, false><<<(NN * FIN / 4 + 255) / 256, 256>>>(x);
    k_convW<<<(FIN * 256 + 255) / 256, 256>>>(Wl[0], FIN, 0);
    k_convW<<<(FIN * 256 + 255) / 256, 256>>>(Wr[0], FIN, 256);
    k_gemm<384><<<ggrid, 512, GEMM_SMEM>>>(bl[0], br[0]);
    k_agg<true><<<abl, 256>>>(att[0], bias[0]);      // packs relu(h) -> g_Ab

    // layer 1 (K=256)
    k_convW<<<wblocks, 256>>>(Wl[1], HC, 0);
    k_convW<<<wblocks, 256>>>(Wr[1], HC, 256);
    k_gemm<768><<<ggrid, 512, GEMM_SMEM>>>(bl[1], br[1]);
    k_agg<true><<<abl, 256>>>(att[1], bias[1]);      // packs relu(h) -> g_Ab

    // layer 2 (K=256)
    k_convW<<<wblocks, 256>>>(Wl[2], HC, 0);
    k_convW<<<wblocks, 256>>>(Wr[2], HC, 256);
    k_gemm<768><<<ggrid, 512, GEMM_SMEM>>>(bl[2], br[2]);
    k_agg<false><<<abl, 256>>>(att[2], bias[2]);     // writes h -> g_H for pooling

    k_cnt<<<(NN + 255) / 256, 256>>>(batch);
    k_pool<<<(NN + 255) / 256, 256>>>(batch);
    k_final<<<1, 64>>>(Wout, bout, out);
}

// round 7
// speedup vs baseline: 1.5073x; 1.0295x over previous
#include <cuda_runtime.h>
#include <cuda_bf16.h>
#include <math_constants.h>
#include <cstdint>

// Problem constants (fixed by the dataset)
#define NN   50000
#define EE   600000
#define EP   (EE + NN)     // edges + self loops = 650000
#define FIN  128
#define HC   256           // H*C = 4*64
#define NG   64            // graphs
#define NCLS 3

#define SMEM_SWIZZLE_128B(b) ((b) ^ (((b) >> 3) & 0x70))

__device__ __forceinline__ uint32_t smem_to_u32(const void* p) {
    uint32_t a;
    asm("{ .reg .u64 t; cvta.to.shared.u64 t, %1; cvt.u32.u64 %0, t; }" : "=r"(a) : "l"(p));
    return a;
}
__device__ __forceinline__ void cp_async16(uint32_t dst, const void* src, bool pred) {
    int sz = pred ? 16 : 0;
    asm volatile("cp.async.cg.shared.global [%0], [%1], 16, %2;"
                 :: "r"(dst), "l"(src), "r"(sz) : "memory");
}
template <int N>
__device__ __forceinline__ void cp_async_wait() {
    asm volatile("cp.async.wait_group %0;" :: "n"(N) : "memory");
}
__device__ __forceinline__ void ldsm_x4(uint32_t* r, uint32_t addr) {
    asm volatile("ldmatrix.sync.aligned.m8n8.x4.shared.b16 {%0,%1,%2,%3}, [%4];"
                 : "=r"(r[0]), "=r"(r[1]), "=r"(r[2]), "=r"(r[3]) : "r"(addr));
}
__device__ __forceinline__ void mma16816(float* c, const uint32_t* a, const uint32_t* b) {
    asm volatile("mma.sync.aligned.m16n8k16.row.col.f32.bf16.bf16.f32 "
                 "{%0,%1,%2,%3}, {%4,%5,%6,%7}, {%8,%9}, {%0,%1,%2,%3};"
                 : "+f"(c[0]), "+f"(c[1]), "+f"(c[2]), "+f"(c[3])
                 : "r"(a[0]), "r"(a[1]), "r"(a[2]), "r"(a[3]), "r"(b[0]), "r"(b[1]));
}

// ---------------- device scratch (no allocation allowed) ----------------
__device__ float g_XL[(size_t)NN * HC];
__device__ float g_XR[(size_t)NN * HC];
__device__ float g_H [(size_t)NN * HC];
__device__ __align__(16) __nv_bfloat16 g_Ab[(size_t)NN * 512];  // A physical [hi|lo], stride 2K
__device__ __align__(16) __nv_bfloat16 g_Wb0[512 * 384];        // layer0 B [Whi|Whi|Wlo]
__device__ __align__(16) __nv_bfloat16 g_Wb1[512 * 768];        // layer1 B
__device__ __align__(16) __nv_bfloat16 g_Wb2[512 * 768];        // layer2 B
__device__ int   g_deg[NN];
__device__ int   g_off[NN];
__device__ int   g_cur[NN];
__device__ int   g_esrc[EP];
__device__ float    g_psum[NG * HC];
__device__ unsigned g_pmax[NG * HC];
__device__ int      g_cnt[NG];

__device__ __forceinline__ unsigned fkey(float f) {
    unsigned b = __float_as_uint(f);
    return (b & 0x80000000u) ? ~b : (b | 0x80000000u);
}
__device__ __forceinline__ float fdekey(unsigned u) {
    return (u & 0x80000000u) ? __uint_as_float(u & 0x7FFFFFFFu) : __uint_as_float(~u);
}

// ---------------- layer-0 input conversion: fp32 -> bf16 [hi|lo], stride 256 ----------------
__global__ void k_convA(const float* __restrict__ in) {
    int i = blockIdx.x * blockDim.x + threadIdx.x;
    if (i >= NN * FIN / 4) return;
    int row = i >> 5, j = (i & 31) * 4;        // FIN/4 = 32
    float4 v = ((const float4*)in)[i];
    __nv_bfloat16 hx = __float2bfloat16(v.x), hy = __float2bfloat16(v.y);
    __nv_bfloat16 hz = __float2bfloat16(v.z), hw = __float2bfloat16(v.w);
    __nv_bfloat162 h01(hx, hy), h23(hz, hw);
    __nv_bfloat162 l01(__float2bfloat16(v.x - __bfloat162float(hx)),
                       __float2bfloat16(v.y - __bfloat162float(hy)));
    __nv_bfloat162 l23(__float2bfloat16(v.z - __bfloat162float(hz)),
                       __float2bfloat16(v.w - __bfloat162float(hw)));
    size_t base = (size_t)row * 256;
    *(__nv_bfloat162*)&g_Ab[base + j]           = h01;
    *(__nv_bfloat162*)&g_Ab[base + j + 2]       = h23;
    *(__nv_bfloat162*)&g_Ab[base + 128 + j]     = l01;
    *(__nv_bfloat162*)&g_Ab[base + 128 + j + 2] = l23;
}

// ---------------- all weight conversions in one launch ----------------
// W [K][256] fp32 -> dst[n][3K] = [Whi | Whi | Wlo], n-major
__global__ void k_convW_all(const float* __restrict__ Wl0, const float* __restrict__ Wr0,
                            const float* __restrict__ Wl1, const float* __restrict__ Wr1,
                            const float* __restrict__ Wl2, const float* __restrict__ Wr2) {
    int y = blockIdx.y;
    int K = (y < 2) ? FIN : HC;
    int i = blockIdx.x * blockDim.x + threadIdx.x;
    if (i >= K * 256) return;
    const float* W;
    __nv_bfloat16* dst;
    switch (y) {
        case 0: W = Wl0; dst = g_Wb0; break;
        case 1: W = Wr0; dst = g_Wb0; break;
        case 2: W = Wl1; dst = g_Wb1; break;
        case 3: W = Wr1; dst = g_Wb1; break;
        case 4: W = Wl2; dst = g_Wb2; break;
        default: W = Wr2; dst = g_Wb2; break;
    }
    int nbase = (y & 1) * 256;
    int k = i >> 8, n = i & 255;
    float v = W[i];
    __nv_bfloat16 h = __float2bfloat16(v);
    __nv_bfloat16 l = __float2bfloat16(v - __bfloat162float(h));
    size_t base = (size_t)(nbase + n) * (3 * K);
    dst[base + k]         = h;
    dst[base + K + k]     = h;
    dst[base + 2 * K + k] = l;
}

// ---------------- init ----------------
__global__ void k_init() {
    int i = blockIdx.x * blockDim.x + threadIdx.x;
    int stride = gridDim.x * blockDim.x;
    for (int j = i; j < NN; j += stride) g_deg[j] = 0;
    for (int j = i; j < NG * HC; j += stride) { g_psum[j] = 0.f; g_pmax[j] = 0x007FFFFFu; }
    for (int j = i; j < NG; j += stride) g_cnt[j] = 0;
}

// ---------------- CSR build (+ graph-count histogram fused) ----------------
__global__ void k_deg(const int* __restrict__ ei, const int* __restrict__ batch) {
    int i = blockIdx.x * blockDim.x + threadIdx.x;
    if (i < NN) atomicAdd(&g_cnt[batch[i]], 1);
    if (i >= EP) return;
    int d = (i < EE) ? ei[EE + i] : (i - EE);
    atomicAdd(&g_deg[d], 1);
}

__global__ void k_scan() {
    __shared__ int wsum[32];
    __shared__ int tot;
    int tid = threadIdx.x, lane = tid & 31, wid = tid >> 5;
    int running = 0;
    for (int base = 0; base < NN; base += 1024) {
        int i = base + tid;
        int v = (i < NN) ? g_deg[i] : 0;
        int x = v;
        #pragma unroll
        for (int o = 1; o < 32; o <<= 1) {
            int t = __shfl_up_sync(0xFFFFFFFFu, x, o);
            if (lane >= o) x += t;
        }
        if (lane == 31) wsum[wid] = x;
        __syncthreads();
        if (wid == 0) {
            int orig = wsum[lane];
            int y = orig;
            #pragma unroll
            for (int o = 1; o < 32; o <<= 1) {
                int t = __shfl_up_sync(0xFFFFFFFFu, y, o);
                if (lane >= o) y += t;
            }
            wsum[lane] = y - orig;
        }
        __syncthreads();
        int incl = x + wsum[wid];
        if (i < NN) {
            int ex = running + incl - v;
            g_off[i] = ex;
            g_cur[i] = ex;
        }
        if (tid == 1023) tot = incl;
        __syncthreads();
        running += tot;
    }
}

__global__ void k_scatter(const int* __restrict__ ei) {
    int i = blockIdx.x * blockDim.x + threadIdx.x;
    if (i >= EP) return;
    int s, d;
    if (i < EE) { s = ei[i]; d = ei[EE + i]; }
    else        { s = d = i - EE; }
    int pos = atomicAdd(&g_cur[d], 1);
    g_esrc[pos] = s;
}

// ---------------- mma.sync bf16 GEMM ----------------
// CTA tile 128 x 256 of the NN x 512 output. 512 threads = 16 warps (4M x 4N).
// 3-stage cp.async pipeline, K-chunk 64.
// Logical K = KLOG = 3K (terms AhiBhi, AloBhi, AhiBlo).
// A physical stride KA = 2K ([hi|lo]); logical chunk c wraps: ka = c*64 mod KA.
// B physical stride KLOG ([Whi|Whi|Wlo]); identity mapping.
#define A_BYTES (128 * 64 * 2)   // 16KB
#define B_BYTES (256 * 64 * 2)   // 32KB
#define GEMM_SMEM (3 * (A_BYTES + B_BYTES))   // 144KB

template <int KLOG, int KA>
__global__ void __launch_bounds__(512, 1) k_gemm(int wsel,
                                                 const float* __restrict__ biasL,
                                                 const float* __restrict__ biasR) {
    extern __shared__ char smem[];
    const __nv_bfloat16* Wb = (wsel == 0) ? g_Wb0 : (wsel == 1) ? g_Wb1 : g_Wb2;
    const int tid = threadIdx.x;
    const int lane = tid & 31, wid = tid >> 5;
    const int m0 = blockIdx.x * 128;
    const int n0 = blockIdx.y * 256;
    const int wm = (wid & 3) * 32;
    const int wn = (wid >> 2) * 64;

    uint32_t sbase = smem_to_u32(smem);

    float acc[2][8][4];
    #pragma unroll
    for (int mt = 0; mt < 2; mt++)
        #pragma unroll
        for (int nt = 0; nt < 8; nt++)
            #pragma unroll
            for (int q = 0; q < 4; q++) acc[mt][nt][q] = 0.f;

    constexpr int NT = KLOG / 64;

    auto issue = [&](int slot, int c) {
        uint32_t ab = sbase + slot * A_BYTES;
        uint32_t bb = sbase + 3 * A_BYTES + slot * B_BYTES;
        int ka = c * 64;
        if (ka >= KA) ka -= KA;                // wrap 3rd phase back onto hi
        int kb = c * 64;
        #pragma unroll
        for (int i = 0; i < 2; i++) {          // A: 1024 16B-chunks
            int chunk = tid + i * 512;
            int row = chunk >> 3, seg = chunk & 7;
            int sw = SMEM_SWIZZLE_128B(row * 128 + seg * 16);
            bool ok = (m0 + row) < NN;
            int grow = ok ? (m0 + row) : 0;
            cp_async16(ab + sw, &g_Ab[(size_t)grow * KA + ka + seg * 8], ok);
        }
        #pragma unroll
        for (int i = 0; i < 4; i++) {          // B: 2048 16B-chunks
            int chunk = tid + i * 512;
            int row = chunk >> 3, seg = chunk & 7;
            int sw = SMEM_SWIZZLE_128B(row * 128 + seg * 16);
            cp_async16(bb + sw, &Wb[(size_t)(n0 + row) * KLOG + kb + seg * 8], true);
        }
        asm volatile("cp.async.commit_group;" ::: "memory");
    };

    issue(0, 0);
    issue(1, 1);

    for (int t = 0; t < NT; t++) {
        if (t + 1 < NT) cp_async_wait<1>(); else cp_async_wait<0>();
        __syncthreads();
        if (t + 2 < NT) issue((t + 2) % 3, t + 2);

        int slot = t % 3;
        uint32_t ab = sbase + slot * A_BYTES;
        uint32_t bb = sbase + 3 * A_BYTES + slot * B_BYTES;
        #pragma unroll
        for (int ks = 0; ks < 4; ks++) {
            int k16 = ks * 16;
            uint32_t a[2][4];
            #pragma unroll
            for (int mt = 0; mt < 2; mt++) {
                int row = wm + mt * 16 + (lane & 15);
                int col = k16 + (lane >> 4) * 8;
                ldsm_x4(a[mt], ab + SMEM_SWIZZLE_128B(row * 128 + col * 2));
            }
            uint32_t b[4][4];
            #pragma unroll
            for (int nt = 0; nt < 4; nt++) {
                int row = wn + nt * 16 + (lane & 7) + ((lane >> 4) << 3);
                int col = k16 + ((lane >> 3) & 1) * 8;
                ldsm_x4(b[nt], bb + SMEM_SWIZZLE_128B(row * 128 + col * 2));
            }
            #pragma unroll
            for (int mt = 0; mt < 2; mt++)
                #pragma unroll
                for (int nt = 0; nt < 8; nt++)
                    mma16816(acc[mt][nt], a[mt], &b[nt >> 1][(nt & 1) * 2]);
        }
    }

    // epilogue: bias add + split XL/XR
    bool halfR = (n0 + wn) >= 256;
    float* outp = halfR ? g_XR : g_XL;
    const float* bias = halfR ? biasR : biasL;
    int cb = n0 + wn - (halfR ? 256 : 0);
    #pragma unroll
    for (int mt = 0; mt < 2; mt++) {
        int r0 = m0 + wm + mt * 16 + (lane >> 2);
        #pragma unroll
        for (int nt = 0; nt < 8; nt++) {
            int c = cb + nt * 8 + (lane & 3) * 2;
            float b0 = bias[c], b1 = bias[c + 1];
            if (r0 < NN)
                *(float2*)&outp[(size_t)r0 * HC + c] =
                    make_float2(acc[mt][nt][0] + b0, acc[mt][nt][1] + b1);
            if (r0 + 8 < NN)
                *(float2*)&outp[(size_t)(r0 + 8) * HC + c] =
                    make_float2(acc[mt][nt][2] + b0, acc[mt][nt][3] + b1);
        }
    }
}

// ---------------- warp-per-node edge softmax + aggregation ----------------
// PACK=true: write relu(h) as bf16 [hi|lo] (stride 512) directly to g_Ab.
// PACK=false: write h (fp32) to g_H (feeds pooling).
template <bool PACK>
__global__ void k_agg(const float* __restrict__ att, const float* __restrict__ bias) {
    int gt = blockIdx.x * blockDim.x + threadIdx.x;
    int node = gt >> 5;
    int lane = gt & 31;
    if (node >= NN) return;

    int fb = lane * 8;

    float4 x0 = *(const float4*)&g_XR[(size_t)node * HC + fb];
    float4 x1 = *(const float4*)&g_XR[(size_t)node * HC + fb + 4];
    float xr[8] = {x0.x, x0.y, x0.z, x0.w, x1.x, x1.y, x1.z, x1.w};
    float4 a0 = *(const float4*)&att[fb];
    float4 a1 = *(const float4*)&att[fb + 4];
    float at[8] = {a0.x, a0.y, a0.z, a0.w, a1.x, a1.y, a1.z, a1.w};

    float acc[8];
    #pragma unroll
    for (int j = 0; j < 8; j++) acc[j] = 0.f;
    float m = -CUDART_INF_F, den = 0.f;

    int st = g_off[node];
    int en = st + g_deg[node];

    int e = st;
    for (; e + 1 < en; e += 2) {
        int s0 = g_esrc[e];
        int s1 = g_esrc[e + 1];
        float4 u0 = *(const float4*)&g_XL[(size_t)s0 * HC + fb];
        float4 u1 = *(const float4*)&g_XL[(size_t)s0 * HC + fb + 4];
        float4 w0v = *(const float4*)&g_XL[(size_t)s1 * HC + fb];
        float4 w1v = *(const float4*)&g_XL[(size_t)s1 * HC + fb + 4];
        float v0[8] = {u0.x, u0.y, u0.z, u0.w, u1.x, u1.y, u1.z, u1.w};
        float v1[8] = {w0v.x, w0v.y, w0v.z, w0v.w, w1v.x, w1v.y, w1v.z, w1v.w};

        float p0 = 0.f, p1 = 0.f;
        #pragma unroll
        for (int j = 0; j < 8; j++) {
            float t0 = v0[j] + xr[j];
            float t1 = v1[j] + xr[j];
            t0 = (t0 > 0.f) ? t0 : 0.2f * t0;
            t1 = (t1 > 0.f) ? t1 : 0.2f * t1;
            p0 = fmaf(t0, at[j], p0);
            p1 = fmaf(t1, at[j], p1);
        }
        #pragma unroll
        for (int o = 1; o <= 4; o <<= 1) {
            p0 += __shfl_xor_sync(0xFFFFFFFFu, p0, o);
            p1 += __shfl_xor_sync(0xFFFFFFFFu, p1, o);
        }

        float mn = fmaxf(m, fmaxf(p0, p1));
        float sc = __expf(m - mn);
        float w0 = __expf(p0 - mn);
        float w1 = __expf(p1 - mn);
        den = fmaf(den, sc, w0 + w1);
        #pragma unroll
        for (int j = 0; j < 8; j++)
            acc[j] = fmaf(acc[j], sc, fmaf(w0, v0[j], w1 * v1[j]));
        m = mn;
    }
    if (e < en) {
        int s = g_esrc[e];
        float4 u0 = *(const float4*)&g_XL[(size_t)s * HC + fb];
        float4 u1 = *(const float4*)&g_XL[(size_t)s * HC + fb + 4];
        float v[8] = {u0.x, u0.y, u0.z, u0.w, u1.x, u1.y, u1.z, u1.w};
        float ps = 0.f;
        #pragma unroll
        for (int j = 0; j < 8; j++) {
            float t = v[j] + xr[j];
            t = (t > 0.f) ? t : 0.2f * t;
            ps = fmaf(t, at[j], ps);
        }
        #pragma unroll
        for (int o = 1; o <= 4; o <<= 1)
            ps += __shfl_xor_sync(0xFFFFFFFFu, ps, o);
        float mn = fmaxf(m, ps);
        float sc = __expf(m - mn);
        float w = __expf(ps - mn);
        den = fmaf(den, sc, w);
        #pragma unroll
        for (int j = 0; j < 8; j++) acc[j] = fmaf(acc[j], sc, w * v[j]);
        m = mn;
    }

    float inv = 1.f / den;
    float4 bb0 = *(const float4*)&bias[fb];
    float4 bb1 = *(const float4*)&bias[fb + 4];
    float bs[8] = {bb0.x, bb0.y, bb0.z, bb0.w, bb1.x, bb1.y, bb1.z, bb1.w};
    float o[8];
    #pragma unroll
    for (int j = 0; j < 8; j++) o[j] = fmaf(acc[j], inv, bs[j]);

    if (PACK) {
        // relu + hi/lo split, packed [hi | lo] with K=256 (stride 512)
        uint32_t hw[4], lw[4];
        #pragma unroll
        for (int i = 0; i < 4; i++) {
            float r0 = fmaxf(o[2 * i], 0.f);
            float r1 = fmaxf(o[2 * i + 1], 0.f);
            __nv_bfloat16 h0 = __float2bfloat16(r0);
            __nv_bfloat16 h1 = __float2bfloat16(r1);
            __nv_bfloat16 l0 = __float2bfloat16(r0 - __bfloat162float(h0));
            __nv_bfloat16 l1 = __float2bfloat16(r1 - __bfloat162float(h1));
            hw[i] = (uint32_t)__bfloat16_as_ushort(h0) |
                    ((uint32_t)__bfloat16_as_ushort(h1) << 16);
            lw[i] = (uint32_t)__bfloat16_as_ushort(l0) |
                    ((uint32_t)__bfloat16_as_ushort(l1) << 16);
        }
        size_t base = (size_t)node * 512 + fb;
        *(uint4*)&g_Ab[base]       = make_uint4(hw[0], hw[1], hw[2], hw[3]);
        *(uint4*)&g_Ab[base + 256] = make_uint4(lw[0], lw[1], lw[2], lw[3]);
    } else {
        *(float4*)&g_H[(size_t)node * HC + fb] =
            make_float4(o[0], o[1], o[2], o[3]);
        *(float4*)&g_H[(size_t)node * HC + fb + 4] =
            make_float4(o[4], o[5], o[6], o[7]);
    }
}

// ---------------- pooling ----------------
__global__ void k_pool(const int* __restrict__ batch) {
    int f = threadIdx.x;
    int n0 = blockIdx.x * 256;
    int n1 = min(n0 + 256, NN);
    int curg = -1;
    float s = 0.f, mx = -CUDART_INF_F;
    for (int n = n0; n < n1; n++) {
        int g = batch[n];
        float v = g_H[(size_t)n * HC + f];
        if (g != curg) {
            if (curg >= 0) {
                atomicAdd(&g_psum[curg * HC + f], s);
                atomicMax(&g_pmax[curg * HC + f], fkey(mx));
            }
            curg = g; s = 0.f; mx = -CUDART_INF_F;
        }
        s += v;
        mx = fmaxf(mx, v);
    }
    if (curg >= 0) {
        atomicAdd(&g_psum[curg * HC + f], s);
        atomicMax(&g_pmax[curg * HC + f], fkey(mx));
    }
}

// ---------------- classifier + softmax ----------------
__global__ void k_final(const float* __restrict__ Wout, const float* __restrict__ bout,
                        float* __restrict__ out) {
    int g = threadIdx.x;
    if (g >= NG) return;
    float c = (float)max(g_cnt[g], 1);
    float inv_c = 1.f / c;
    float l0 = bout[0], l1 = bout[1], l2 = bout[2];
    for (int f = 0; f < HC; f++) {
        float p = g_psum[g * HC + f] * inv_c + fdekey(g_pmax[g * HC + f]);
        l0 = fmaf(p, Wout[f * NCLS + 0], l0);
        l1 = fmaf(p, Wout[f * NCLS + 1], l1);
        l2 = fmaf(p, Wout[f * NCLS + 2], l2);
    }
    float mx = fmaxf(l0, fmaxf(l1, l2));
    float e0 = __expf(l0 - mx), e1 = __expf(l1 - mx), e2 = __expf(l2 - mx);
    float inv = 1.f / (e0 + e1 + e2);
    out[g * NCLS + 0] = e0 * inv;
    out[g * NCLS + 1] = e1 * inv;
    out[g * NCLS + 2] = e2 * inv;
}

// ---------------- launch ----------------
extern "C" void kernel_launch(void* const* d_in, const int* in_sizes, int n_in,
                              void* d_out, int out_size) {
    const float* x     = (const float*)d_in[0];
    const int*   ei    = (const int*)d_in[1];
    const int*   batch = (const int*)d_in[2];
    const float* Wl[3]   = {(const float*)d_in[3],  (const float*)d_in[9],  (const float*)d_in[15]};
    const float* bl[3]   = {(const float*)d_in[4],  (const float*)d_in[10], (const float*)d_in[16]};
    const float* Wr[3]   = {(const float*)d_in[5],  (const float*)d_in[11], (const float*)d_in[17]};
    const float* br[3]   = {(const float*)d_in[6],  (const float*)d_in[12], (const float*)d_in[18]};
    const float* att[3]  = {(const float*)d_in[7],  (const float*)d_in[13], (const float*)d_in[19]};
    const float* bias[3] = {(const float*)d_in[8],  (const float*)d_in[14], (const float*)d_in[20]};
    const float* Wout    = (const float*)d_in[21];
    const float* bout    = (const float*)d_in[22];
    float* out = (float*)d_out;

    (void)in_sizes; (void)n_in; (void)out_size;

    static bool attr_done = false;
    if (!attr_done) {
        cudaFuncSetAttribute((const void*)k_gemm<384, 256>,
                             cudaFuncAttributeMaxDynamicSharedMemorySize, GEMM_SMEM);
        cudaFuncSetAttribute((const void*)k_gemm<768, 512>,
                             cudaFuncAttributeMaxDynamicSharedMemorySize, GEMM_SMEM);
        attr_done = true;
    }

    dim3 ggrid((NN + 127) / 128, 2);
    int abl = (NN * 32 + 255) / 256;
    int ebl = (EP + 255) / 256;

    // 1-2: conversions (no CSR dependency)
    k_convA<<<(NN * FIN / 4 + 255) / 256, 256>>>(x);
    k_convW_all<<<dim3(256, 6), 256>>>(Wl[0], Wr[0], Wl[1], Wr[1], Wl[2], Wr[2]);
    // 3: init (deg/psum/pmax/cnt)
    k_init<<<256, 256>>>();
    // 4: layer-0 GEMM  <-- target of the ncu capture slot
    k_gemm<384, 256><<<ggrid, 512, GEMM_SMEM>>>(0, bl[0], br[0]);
    // 5-7: CSR build (+cnt fused into deg)
    k_deg<<<ebl, 256>>>(ei, batch);
    k_scan<<<1, 1024>>>();
    k_scatter<<<ebl, 256>>>(ei);
    // 8: layer-0 aggregation (packs relu(h) -> g_Ab)
    k_agg<true><<<abl, 256>>>(att[0], bias[0]);
    // 9-10: layer 1
    k_gemm<768, 512><<<ggrid, 512, GEMM_SMEM>>>(1, bl[1], br[1]);
    k_agg<true><<<abl, 256>>>(att[1], bias[1]);
    // 11-12: layer 2
    k_gemm<768, 512><<<ggrid, 512, GEMM_SMEM>>>(2, bl[2], br[2]);
    k_agg<false><<<abl, 256>>>(att[2], bias[2]);
    // 13-14: pooling + classifier
    k_pool<<<(NN + 255) / 256, 256>>>(batch);
    k_final<<<1, 64>>>(Wout, bout, out);
}

// round 8
// speedup vs baseline: 1.6071x; 1.0662x over previous
#include <cuda_runtime.h>
#include <cuda_bf16.h>
#include <math_constants.h>
#include <cstdint>

// Problem constants (fixed by the dataset)
#define NN   50000
#define EE   600000
#define EP   (EE + NN)     // edges + self loops = 650000
#define FIN  128
#define HC   256           // H*C = 4*64
#define NG   64            // graphs
#define NCLS 3

#define SMEM_SWIZZLE_128B(b) ((b) ^ (((b) >> 3) & 0x70))

__device__ __forceinline__ uint32_t smem_to_u32(const void* p) {
    uint32_t a;
    asm("{ .reg .u64 t; cvta.to.shared.u64 t, %1; cvt.u32.u64 %0, t; }" : "=r"(a) : "l"(p));
    return a;
}
__device__ __forceinline__ void cp_async16(uint32_t dst, const void* src, bool pred) {
    int sz = pred ? 16 : 0;
    asm volatile("cp.async.cg.shared.global [%0], [%1], 16, %2;"
                 :: "r"(dst), "l"(src), "r"(sz) : "memory");
}
template <int N>
__device__ __forceinline__ void cp_async_wait() {
    asm volatile("cp.async.wait_group %0;" :: "n"(N) : "memory");
}
__device__ __forceinline__ void ldsm_x4(uint32_t* r, uint32_t addr) {
    asm volatile("ldmatrix.sync.aligned.m8n8.x4.shared.b16 {%0,%1,%2,%3}, [%4];"
                 : "=r"(r[0]), "=r"(r[1]), "=r"(r[2]), "=r"(r[3]) : "r"(addr));
}
__device__ __forceinline__ void mma16816(float* c, const uint32_t* a, const uint32_t* b) {
    asm volatile("mma.sync.aligned.m16n8k16.row.col.f32.bf16.bf16.f32 "
                 "{%0,%1,%2,%3}, {%4,%5,%6,%7}, {%8,%9}, {%0,%1,%2,%3};"
                 : "+f"(c[0]), "+f"(c[1]), "+f"(c[2]), "+f"(c[3])
                 : "r"(a[0]), "r"(a[1]), "r"(a[2]), "r"(a[3]), "r"(b[0]), "r"(b[1]));
}

// ---------------- device scratch (no allocation allowed) ----------------
__device__ float g_XL[(size_t)NN * HC];
__device__ float g_XR[(size_t)NN * HC];
__device__ float g_H [(size_t)NN * HC];
__device__ __align__(16) __nv_bfloat16 g_Ab[(size_t)NN * 512];  // A physical [hi|lo], stride 2K
__device__ __align__(16) __nv_bfloat16 g_Wb0[512 * 384];        // layer0 B [Whi|Whi|Wlo]
__device__ __align__(16) __nv_bfloat16 g_Wb1[512 * 768];        // layer1 B
__device__ __align__(16) __nv_bfloat16 g_Wb2[512 * 768];        // layer2 B
__device__ int   g_deg[NN];
__device__ int   g_off[NN];
__device__ int   g_cur[NN];
__device__ int   g_esrc[EP];
__device__ float    g_psum[NG * HC];
__device__ unsigned g_pmax[NG * HC];
__device__ int      g_cnt[NG];

__device__ __forceinline__ unsigned fkey(float f) {
    unsigned b = __float_as_uint(f);
    return (b & 0x80000000u) ? ~b : (b | 0x80000000u);
}
__device__ __forceinline__ float fdekey(unsigned u) {
    return (u & 0x80000000u) ? __uint_as_float(u & 0x7FFFFFFFu) : __uint_as_float(~u);
}

// ---------------- layer-0 input conversion: fp32 -> bf16 [hi|lo], stride 256 ----------------
__global__ void k_convA(const float* __restrict__ in) {
    int i = blockIdx.x * blockDim.x + threadIdx.x;
    if (i >= NN * FIN / 4) return;
    int row = i >> 5, j = (i & 31) * 4;        // FIN/4 = 32
    float4 v = ((const float4*)in)[i];
    __nv_bfloat16 hx = __float2bfloat16(v.x), hy = __float2bfloat16(v.y);
    __nv_bfloat16 hz = __float2bfloat16(v.z), hw = __float2bfloat16(v.w);
    __nv_bfloat162 h01(hx, hy), h23(hz, hw);
    __nv_bfloat162 l01(__float2bfloat16(v.x - __bfloat162float(hx)),
                       __float2bfloat16(v.y - __bfloat162float(hy)));
    __nv_bfloat162 l23(__float2bfloat16(v.z - __bfloat162float(hz)),
                       __float2bfloat16(v.w - __bfloat162float(hw)));
    size_t base = (size_t)row * 256;
    *(__nv_bfloat162*)&g_Ab[base + j]           = h01;
    *(__nv_bfloat162*)&g_Ab[base + j + 2]       = h23;
    *(__nv_bfloat162*)&g_Ab[base + 128 + j]     = l01;
    *(__nv_bfloat162*)&g_Ab[base + 128 + j + 2] = l23;
}

// ---------------- all weight conversions in one launch ----------------
// W [K][256] fp32 -> dst[n][3K] = [Whi | Whi | Wlo], n-major
__global__ void k_convW_all(const float* __restrict__ Wl0, const float* __restrict__ Wr0,
                            const float* __restrict__ Wl1, const float* __restrict__ Wr1,
                            const float* __restrict__ Wl2, const float* __restrict__ Wr2) {
    int y = blockIdx.y;
    int K = (y < 2) ? FIN : HC;
    int i = blockIdx.x * blockDim.x + threadIdx.x;
    if (i >= K * 256) return;
    const float* W;
    __nv_bfloat16* dst;
    switch (y) {
        case 0: W = Wl0; dst = g_Wb0; break;
        case 1: W = Wr0; dst = g_Wb0; break;
        case 2: W = Wl1; dst = g_Wb1; break;
        case 3: W = Wr1; dst = g_Wb1; break;
        case 4: W = Wl2; dst = g_Wb2; break;
        default: W = Wr2; dst = g_Wb2; break;
    }
    int nbase = (y & 1) * 256;
    int k = i >> 8, n = i & 255;
    float v = W[i];
    __nv_bfloat16 h = __float2bfloat16(v);
    __nv_bfloat16 l = __float2bfloat16(v - __bfloat162float(h));
    size_t base = (size_t)(nbase + n) * (3 * K);
    dst[base + k]         = h;
    dst[base + K + k]     = h;
    dst[base + 2 * K + k] = l;
}

// ---------------- init ----------------
__global__ void k_init() {
    int i = blockIdx.x * blockDim.x + threadIdx.x;
    int stride = gridDim.x * blockDim.x;
    for (int j = i; j < NN; j += stride) g_deg[j] = 0;
    for (int j = i; j < NG * HC; j += stride) { g_psum[j] = 0.f; g_pmax[j] = 0x007FFFFFu; }
    for (int j = i; j < NG; j += stride) g_cnt[j] = 0;
}

// ---------------- CSR build (+ graph-count histogram fused) ----------------
__global__ void k_deg(const int* __restrict__ ei, const int* __restrict__ batch) {
    int i = blockIdx.x * blockDim.x + threadIdx.x;
    if (i < NN) atomicAdd(&g_cnt[batch[i]], 1);
    if (i >= EP) return;
    int d = (i < EE) ? ei[EE + i] : (i - EE);
    atomicAdd(&g_deg[d], 1);
}

__global__ void k_scan() {
    __shared__ int wsum[32];
    __shared__ int tot;
    int tid = threadIdx.x, lane = tid & 31, wid = tid >> 5;
    int running = 0;
    for (int base = 0; base < NN; base += 1024) {
        int i = base + tid;
        int v = (i < NN) ? g_deg[i] : 0;
        int x = v;
        #pragma unroll
        for (int o = 1; o < 32; o <<= 1) {
            int t = __shfl_up_sync(0xFFFFFFFFu, x, o);
            if (lane >= o) x += t;
        }
        if (lane == 31) wsum[wid] = x;
        __syncthreads();
        if (wid == 0) {
            int orig = wsum[lane];
            int y = orig;
            #pragma unroll
            for (int o = 1; o < 32; o <<= 1) {
                int t = __shfl_up_sync(0xFFFFFFFFu, y, o);
                if (lane >= o) y += t;
            }
            wsum[lane] = y - orig;
        }
        __syncthreads();
        int incl = x + wsum[wid];
        if (i < NN) {
            int ex = running + incl - v;
            g_off[i] = ex;
            g_cur[i] = ex;
        }
        if (tid == 1023) tot = incl;
        __syncthreads();
        running += tot;
    }
}

__global__ void k_scatter(const int* __restrict__ ei) {
    int i = blockIdx.x * blockDim.x + threadIdx.x;
    if (i >= EP) return;
    int s, d;
    if (i < EE) { s = ei[i]; d = ei[EE + i]; }
    else        { s = d = i - EE; }
    int pos = atomicAdd(&g_cur[d], 1);
    g_esrc[pos] = s;
}

// ---------------- mma.sync bf16 GEMM ----------------
// CTA tile 128 x 128 of the NN x 512 output. 256 threads = 8 warps (4M x 2N),
// warp tile 32x64. 3-stage cp.async pipeline, K-chunk 64. Sized for 2 CTAs/SM:
// smem 96KB/CTA, regs capped at 128 via __launch_bounds__(256, 2).
// Logical K = KLOG = 3K (terms AhiBhi, AloBhi, AhiBlo).
// A physical stride KA = 2K ([hi|lo]); logical chunk c wraps: ka = c*64 mod KA.
// B physical stride KLOG ([Whi|Whi|Wlo]); identity mapping.
#define A_BYTES (128 * 64 * 2)   // 16KB
#define B_BYTES (128 * 64 * 2)   // 16KB
#define GEMM_SMEM (3 * (A_BYTES + B_BYTES))   // 96KB

template <int KLOG, int KA>
__global__ void __launch_bounds__(256, 2) k_gemm(int wsel,
                                                 const float* __restrict__ biasL,
                                                 const float* __restrict__ biasR) {
    extern __shared__ char smem[];
    const __nv_bfloat16* Wb = (wsel == 0) ? g_Wb0 : (wsel == 1) ? g_Wb1 : g_Wb2;
    const int tid = threadIdx.x;
    const int lane = tid & 31, wid = tid >> 5;
    const int m0 = blockIdx.x * 128;
    const int n0 = blockIdx.y * 128;
    const int wm = (wid & 3) * 32;
    const int wn = (wid >> 2) * 64;

    uint32_t sbase = smem_to_u32(smem);

    float acc[2][8][4];
    #pragma unroll
    for (int mt = 0; mt < 2; mt++)
        #pragma unroll
        for (int nt = 0; nt < 8; nt++)
            #pragma unroll
            for (int q = 0; q < 4; q++) acc[mt][nt][q] = 0.f;

    constexpr int NT = KLOG / 64;

    auto issue = [&](int slot, int c) {
        uint32_t ab = sbase + slot * A_BYTES;
        uint32_t bb = sbase + 3 * A_BYTES + slot * B_BYTES;
        int ka = c * 64;
        if (ka >= KA) ka -= KA;                // wrap 3rd phase back onto hi
        int kb = c * 64;
        #pragma unroll
        for (int i = 0; i < 4; i++) {          // A: 1024 16B-chunks
            int chunk = tid + i * 256;
            int row = chunk >> 3, seg = chunk & 7;
            int sw = SMEM_SWIZZLE_128B(row * 128 + seg * 16);
            bool ok = (m0 + row) < NN;
            int grow = ok ? (m0 + row) : 0;
            cp_async16(ab + sw, &g_Ab[(size_t)grow * KA + ka + seg * 8], ok);
        }
        #pragma unroll
        for (int i = 0; i < 4; i++) {          // B: 1024 16B-chunks
            int chunk = tid + i * 256;
            int row = chunk >> 3, seg = chunk & 7;
            int sw = SMEM_SWIZZLE_128B(row * 128 + seg * 16);
            cp_async16(bb + sw, &Wb[(size_t)(n0 + row) * KLOG + kb + seg * 8], true);
        }
        asm volatile("cp.async.commit_group;" ::: "memory");
    };

    issue(0, 0);
    issue(1, 1);

    for (int t = 0; t < NT; t++) {
        if (t + 1 < NT) cp_async_wait<1>(); else cp_async_wait<0>();
        __syncthreads();
        if (t + 2 < NT) issue((t + 2) % 3, t + 2);

        int slot = t % 3;
        uint32_t ab = sbase + slot * A_BYTES;
        uint32_t bb = sbase + 3 * A_BYTES + slot * B_BYTES;
        #pragma unroll
        for (int ks = 0; ks < 4; ks++) {
            int k16 = ks * 16;
            uint32_t a[2][4];
            #pragma unroll
            for (int mt = 0; mt < 2; mt++) {
                int row = wm + mt * 16 + (lane & 15);
                int col = k16 + (lane >> 4) * 8;
                ldsm_x4(a[mt], ab + SMEM_SWIZZLE_128B(row * 128 + col * 2));
            }
            uint32_t b[4][4];
            #pragma unroll
            for (int nt = 0; nt < 4; nt++) {
                int row = wn + nt * 16 + (lane & 7) + ((lane >> 4) << 3);
                int col = k16 + ((lane >> 3) & 1) * 8;
                ldsm_x4(b[nt], bb + SMEM_SWIZZLE_128B(row * 128 + col * 2));
            }
            #pragma unroll
            for (int mt = 0; mt < 2; mt++)
                #pragma unroll
                for (int nt = 0; nt < 8; nt++)
                    mma16816(acc[mt][nt], a[mt], &b[nt >> 1][(nt & 1) * 2]);
        }
    }

    // epilogue: bias add + split XL/XR
    bool halfR = (n0 + wn) >= 256;
    float* outp = halfR ? g_XR : g_XL;
    const float* bias = halfR ? biasR : biasL;
    int cb = n0 + wn - (halfR ? 256 : 0);
    #pragma unroll
    for (int mt = 0; mt < 2; mt++) {
        int r0 = m0 + wm + mt * 16 + (lane >> 2);
        #pragma unroll
        for (int nt = 0; nt < 8; nt++) {
            int c = cb + nt * 8 + (lane & 3) * 2;
            float b0 = bias[c], b1 = bias[c + 1];
            if (r0 < NN)
                *(float2*)&outp[(size_t)r0 * HC + c] =
                    make_float2(acc[mt][nt][0] + b0, acc[mt][nt][1] + b1);
            if (r0 + 8 < NN)
                *(float2*)&outp[(size_t)(r0 + 8) * HC + c] =
                    make_float2(acc[mt][nt][2] + b0, acc[mt][nt][3] + b1);
        }
    }
}

// ---------------- warp-per-node edge softmax + aggregation ----------------
// PACK=true: write relu(h) as bf16 [hi|lo] (stride 512) directly to g_Ab.
// PACK=false: write h (fp32) to g_H (feeds pooling).
template <bool PACK>
__global__ void k_agg(const float* __restrict__ att, const float* __restrict__ bias) {
    int gt = blockIdx.x * blockDim.x + threadIdx.x;
    int node = gt >> 5;
    int lane = gt & 31;
    if (node >= NN) return;

    int fb = lane * 8;

    float4 x0 = *(const float4*)&g_XR[(size_t)node * HC + fb];
    float4 x1 = *(const float4*)&g_XR[(size_t)node * HC + fb + 4];
    float xr[8] = {x0.x, x0.y, x0.z, x0.w, x1.x, x1.y, x1.z, x1.w};
    float4 a0 = *(const float4*)&att[fb];
    float4 a1 = *(const float4*)&att[fb + 4];
    float at[8] = {a0.x, a0.y, a0.z, a0.w, a1.x, a1.y, a1.z, a1.w};

    float acc[8];
    #pragma unroll
    for (int j = 0; j < 8; j++) acc[j] = 0.f;
    float m = -CUDART_INF_F, den = 0.f;

    int st = g_off[node];
    int en = st + g_deg[node];

    int e = st;
    for (; e + 1 < en; e += 2) {
        int s0 = g_esrc[e];
        int s1 = g_esrc[e + 1];
        float4 u0 = *(const float4*)&g_XL[(size_t)s0 * HC + fb];
        float4 u1 = *(const float4*)&g_XL[(size_t)s0 * HC + fb + 4];
        float4 w0v = *(const float4*)&g_XL[(size_t)s1 * HC + fb];
        float4 w1v = *(const float4*)&g_XL[(size_t)s1 * HC + fb + 4];
        float v0[8] = {u0.x, u0.y, u0.z, u0.w, u1.x, u1.y, u1.z, u1.w};
        float v1[8] = {w0v.x, w0v.y, w0v.z, w0v.w, w1v.x, w1v.y, w1v.z, w1v.w};

        float p0 = 0.f, p1 = 0.f;
        #pragma unroll
        for (int j = 0; j < 8; j++) {
            float t0 = v0[j] + xr[j];
            float t1 = v1[j] + xr[j];
            t0 = (t0 > 0.f) ? t0 : 0.2f * t0;
            t1 = (t1 > 0.f) ? t1 : 0.2f * t1;
            p0 = fmaf(t0, at[j], p0);
            p1 = fmaf(t1, at[j], p1);
        }
        #pragma unroll
        for (int o = 1; o <= 4; o <<= 1) {
            p0 += __shfl_xor_sync(0xFFFFFFFFu, p0, o);
            p1 += __shfl_xor_sync(0xFFFFFFFFu, p1, o);
        }

        float mn = fmaxf(m, fmaxf(p0, p1));
        float sc = __expf(m - mn);
        float w0 = __expf(p0 - mn);
        float w1 = __expf(p1 - mn);
        den = fmaf(den, sc, w0 + w1);
        #pragma unroll
        for (int j = 0; j < 8; j++)
            acc[j] = fmaf(acc[j], sc, fmaf(w0, v0[j], w1 * v1[j]));
        m = mn;
    }
    if (e < en) {
        int s = g_esrc[e];
        float4 u0 = *(const float4*)&g_XL[(size_t)s * HC + fb];
        float4 u1 = *(const float4*)&g_XL[(size_t)s * HC + fb + 4];
        float v[8] = {u0.x, u0.y, u0.z, u0.w, u1.x, u1.y, u1.z, u1.w};
        float ps = 0.f;
        #pragma unroll
        for (int j = 0; j < 8; j++) {
            float t = v[j] + xr[j];
            t = (t > 0.f) ? t : 0.2f * t;
            ps = fmaf(t, at[j], ps);
        }
        #pragma unroll
        for (int o = 1; o <= 4; o <<= 1)
            ps += __shfl_xor_sync(0xFFFFFFFFu, ps, o);
        float mn = fmaxf(m, ps);
        float sc = __expf(m - mn);
        float w = __expf(ps - mn);
        den = fmaf(den, sc, w);
        #pragma unroll
        for (int j = 0; j < 8; j++) acc[j] = fmaf(acc[j], sc, w * v[j]);
        m = mn;
    }

    float inv = 1.f / den;
    float4 bb0 = *(const float4*)&bias[fb];
    float4 bb1 = *(const float4*)&bias[fb + 4];
    float bs[8] = {bb0.x, bb0.y, bb0.z, bb0.w, bb1.x, bb1.y, bb1.z, bb1.w};
    float o[8];
    #pragma unroll
    for (int j = 0; j < 8; j++) o[j] = fmaf(acc[j], inv, bs[j]);

    if (PACK) {
        // relu + hi/lo split, packed [hi | lo] with K=256 (stride 512)
        uint32_t hw[4], lw[4];
        #pragma unroll
        for (int i = 0; i < 4; i++) {
            float r0 = fmaxf(o[2 * i], 0.f);
            float r1 = fmaxf(o[2 * i + 1], 0.f);
            __nv_bfloat16 h0 = __float2bfloat16(r0);
            __nv_bfloat16 h1 = __float2bfloat16(r1);
            __nv_bfloat16 l0 = __float2bfloat16(r0 - __bfloat162float(h0));
            __nv_bfloat16 l1 = __float2bfloat16(r1 - __bfloat162float(h1));
            hw[i] = (uint32_t)__bfloat16_as_ushort(h0) |
                    ((uint32_t)__bfloat16_as_ushort(h1) << 16);
            lw[i] = (uint32_t)__bfloat16_as_ushort(l0) |
                    ((uint32_t)__bfloat16_as_ushort(l1) << 16);
        }
        size_t base = (size_t)node * 512 + fb;
        *(uint4*)&g_Ab[base]       = make_uint4(hw[0], hw[1], hw[2], hw[3]);
        *(uint4*)&g_Ab[base + 256] = make_uint4(lw[0], lw[1], lw[2], lw[3]);
    } else {
        *(float4*)&g_H[(size_t)node * HC + fb] =
            make_float4(o[0], o[1], o[2], o[3]);
        *(float4*)&g_H[(size_t)node * HC + fb + 4] =
            make_float4(o[4], o[5], o[6], o[7]);
    }
}

// ---------------- pooling ----------------
__global__ void k_pool(const int* __restrict__ batch) {
    int f = threadIdx.x;
    int n0 = blockIdx.x * 256;
    int n1 = min(n0 + 256, NN);
    int curg = -1;
    float s = 0.f, mx = -CUDART_INF_F;
    for (int n = n0; n < n1; n++) {
        int g = batch[n];
        float v = g_H[(size_t)n * HC + f];
        if (g != curg) {
            if (curg >= 0) {
                atomicAdd(&g_psum[curg * HC + f], s);
                atomicMax(&g_pmax[curg * HC + f], fkey(mx));
            }
            curg = g; s = 0.f; mx = -CUDART_INF_F;
        }
        s += v;
        mx = fmaxf(mx, v);
    }
    if (curg >= 0) {
        atomicAdd(&g_psum[curg * HC + f], s);
        atomicMax(&g_pmax[curg * HC + f], fkey(mx));
    }
}

// ---------------- classifier + softmax ----------------
__global__ void k_final(const float* __restrict__ Wout, const float* __restrict__ bout,
                        float* __restrict__ out) {
    int g = threadIdx.x;
    if (g >= NG) return;
    float c = (float)max(g_cnt[g], 1);
    float inv_c = 1.f / c;
    float l0 = bout[0], l1 = bout[1], l2 = bout[2];
    for (int f = 0; f < HC; f++) {
        float p = g_psum[g * HC + f] * inv_c + fdekey(g_pmax[g * HC + f]);
        l0 = fmaf(p, Wout[f * NCLS + 0], l0);
        l1 = fmaf(p, Wout[f * NCLS + 1], l1);
        l2 = fmaf(p, Wout[f * NCLS + 2], l2);
    }
    float mx = fmaxf(l0, fmaxf(l1, l2));
    float e0 = __expf(l0 - mx), e1 = __expf(l1 - mx), e2 = __expf(l2 - mx);
    float inv = 1.f / (e0 + e1 + e2);
    out[g * NCLS + 0] = e0 * inv;
    out[g * NCLS + 1] = e1 * inv;
    out[g * NCLS + 2] = e2 * inv;
}

// ---------------- launch ----------------
extern "C" void kernel_launch(void* const* d_in, const int* in_sizes, int n_in,
                              void* d_out, int out_size) {
    const float* x     = (const float*)d_in[0];
    const int*   ei    = (const int*)d_in[1];
    const int*   batch = (const int*)d_in[2];
    const float* Wl[3]   = {(const float*)d_in[3],  (const float*)d_in[9],  (const float*)d_in[15]};
    const float* bl[3]   = {(const float*)d_in[4],  (const float*)d_in[10], (const float*)d_in[16]};
    const float* Wr[3]   = {(const float*)d_in[5],  (const float*)d_in[11], (const float*)d_in[17]};
    const float* br[3]   = {(const float*)d_in[6],  (const float*)d_in[12], (const float*)d_in[18]};
    const float* att[3]  = {(const float*)d_in[7],  (const float*)d_in[13], (const float*)d_in[19]};
    const float* bias[3] = {(const float*)d_in[8],  (const float*)d_in[14], (const float*)d_in[20]};
    const float* Wout    = (const float*)d_in[21];
    const float* bout    = (const float*)d_in[22];
    float* out = (float*)d_out;

    (void)in_sizes; (void)n_in; (void)out_size;

    static bool attr_done = false;
    if (!attr_done) {
        cudaFuncSetAttribute((const void*)k_gemm<384, 256>,
                             cudaFuncAttributeMaxDynamicSharedMemorySize, GEMM_SMEM);
        cudaFuncSetAttribute((const void*)k_gemm<768, 512>,
                             cudaFuncAttributeMaxDynamicSharedMemorySize, GEMM_SMEM);
        attr_done = true;
    }

    dim3 ggrid((NN + 127) / 128, 4);
    int abl = (NN * 32 + 255) / 256;
    int ebl = (EP + 255) / 256;

    // 1-2: conversions (no CSR dependency)
    k_convA<<<(NN * FIN / 4 + 255) / 256, 256>>>(x);
    k_convW_all<<<dim3(256, 6), 256>>>(Wl[0], Wr[0], Wl[1], Wr[1], Wl[2], Wr[2]);
    // 3: init (deg/psum/pmax/cnt)
    k_init<<<256, 256>>>();
    // 4: layer-0 GEMM  <-- ncu capture slot
    k_gemm<384, 256><<<ggrid, 256, GEMM_SMEM>>>(0, bl[0], br[0]);
    // 5-7: CSR build (+cnt fused into deg)
    k_deg<<<ebl, 256>>>(ei, batch);
    k_scan<<<1, 1024>>>();
    k_scatter<<<ebl, 256>>>(ei);
    // 8: layer-0 aggregation (packs relu(h) -> g_Ab)
    k_agg<true><<<abl, 256>>>(att[0], bias[0]);
    // 9-10: layer 1
    k_gemm<768, 512><<<ggrid, 256, GEMM_SMEM>>>(1, bl[1], br[1]);
    k_agg<true><<<abl, 256>>>(att[1], bias[1]);
    // 11-12: layer 2
    k_gemm<768, 512><<<ggrid, 256, GEMM_SMEM>>>(2, bl[2], br[2]);
    k_agg<false><<<abl, 256>>>(att[2], bias[2]);
    // 13-14: pooling + classifier
    k_pool<<<(NN + 255) / 256, 256>>>(batch);
    k_final<<<1, 64>>>(Wout, bout, out);
}